// round 11
// baseline (speedup 1.0000x reference)
#include <cuda_runtime.h>
#include <cuda_bf16.h>
#include <cuda_fp16.h>
#include <cstdint>

#define NN 50000
#define EE 800000
#define ST 256          // padded column stride of fused GEMM output
// tmp row layout: [0:128) hs (2 heads x 64), [128:192) skip = x@Wl,
//                 [192:194) als, [194:196) ald, [196:256) zero pad

__device__ __align__(128) float g_tmp[NN * ST];
__device__ __align__(128) float g_h1[NN * 64];
__device__ __align__(128) float g_h2[NN * 64];
__device__ __align__(128) float4 g_att[NN];            // {als0, als1, ald0, ald1}
__device__ __align__(128) __half g_hsh[NN * 128];      // hs in fp16 for the edge gather
__device__ __align__(128) uint16_t g_xh[NN * 128];     // layer input, bf16 hi
__device__ __align__(128) uint16_t g_xl[NN * 128];     // layer input, bf16 lo (residual)
__device__ __align__(128) uint16_t g_wThb[256 * 128];  // transposed fused weights, bf16 hi
__device__ __align__(128) uint16_t g_wTlb[256 * 128];  // transposed fused weights, bf16 lo
__device__ int g_off[NN + 1];
__device__ int g_cur[NN];
__device__ int g_srcs[EE];

// ---------------- CSR build (by destination) ----------------

__global__ void zero_cnt_kernel() {
    int i = blockIdx.x * blockDim.x + threadIdx.x;
    if (i < NN) g_cur[i] = 0;
}

__global__ void count_kernel(const int* __restrict__ dst) {
    int e = blockIdx.x * blockDim.x + threadIdx.x;
    if (e < EE) atomicAdd(&g_cur[dst[e]], 1);
}

__global__ void scan_kernel() {
    __shared__ int part[1024];
    int tid = threadIdx.x;
    const int CH = (NN + 1023) / 1024;
    int base = tid * CH;
    int s = 0;
    for (int j = 0; j < CH; j++) {
        int i = base + j;
        if (i < NN) s += g_cur[i];
    }
    part[tid] = s;
    __syncthreads();
    if (tid == 0) {
        int r = 0;
        for (int i = 0; i < 1024; i++) { int t = part[i]; part[i] = r; r += t; }
        g_off[NN] = r;
    }
    __syncthreads();
    int r = part[tid];
    for (int j = 0; j < CH; j++) {
        int i = base + j;
        if (i < NN) {
            int d = g_cur[i];
            g_off[i] = r;
            g_cur[i] = r;   // cursor for fill pass
            r += d;
        }
    }
}

__global__ void fill_kernel(const int* __restrict__ src, const int* __restrict__ dst) {
    int e = blockIdx.x * blockDim.x + threadIdx.x;
    if (e < EE) {
        int p = atomicAdd(&g_cur[dst[e]], 1);
        g_srcs[p] = src[e];
    }
}

// ---------------- bf16 split helpers ----------------

__device__ __forceinline__ void bf16_split(float v, uint16_t& hi, uint16_t& lo) {
    __nv_bfloat16 h = __float2bfloat16(v);
    float r = v - __bfloat162float(h);
    __nv_bfloat16 l = __float2bfloat16(r);
    hi = *reinterpret_cast<uint16_t*>(&h);
    lo = *reinterpret_cast<uint16_t*>(&l);
}

// split layer-1 input x [NN,128] into bf16 hi/lo
__global__ void split_x_kernel(const float* __restrict__ x) {
    int t = blockIdx.x * blockDim.x + threadIdx.x;
    if (t >= NN * 32) return;
    float4 v = *(const float4*)&x[t * 4];
    uint16_t h[4], l[4];
    bf16_split(v.x, h[0], l[0]);
    bf16_split(v.y, h[1], l[1]);
    bf16_split(v.z, h[2], l[2]);
    bf16_split(v.w, h[3], l[3]);
    uint2 hp, lp;
    hp.x = (uint32_t)h[0] | ((uint32_t)h[1] << 16);
    hp.y = (uint32_t)h[2] | ((uint32_t)h[3] << 16);
    lp.x = (uint32_t)l[0] | ((uint32_t)l[1] << 16);
    lp.y = (uint32_t)l[2] | ((uint32_t)l[3] << 16);
    *(uint2*)&g_xh[t * 4] = hp;
    *(uint2*)&g_xl[t * 4] = lp;
}

// ---------------- fused weight concat -> transposed bf16 hi/lo ----------------

__global__ void wcat_kernel(const float* __restrict__ Ws, const float* __restrict__ Wd,
                            const float* __restrict__ Wl, const float* __restrict__ as_,
                            const float* __restrict__ ad_, int din) {
    int t = blockIdx.x * blockDim.x + threadIdx.x;
    if (t >= din * 256) return;
    int k = t >> 8, col = t & 255;
    float v = 0.f;
    if (col < 128) {
        v = Ws[k * 128 + col];
    } else if (col < 192) {
        v = Wl[k * 64 + (col - 128)];
    } else if (col < 194) {
        int h = col - 192;
        float s = 0.f;
        for (int c = 0; c < 64; c++) s += Ws[k * 128 + h * 64 + c] * as_[h * 64 + c];
        v = s;
    } else if (col < 196) {
        int h = col - 194;
        float s = 0.f;
        for (int c = 0; c < 64; c++) s += Wd[k * 128 + h * 64 + c] * ad_[h * 64 + c];
        v = s;
    }
    uint16_t hi, lo;
    bf16_split(v, hi, lo);
    g_wThb[col * 128 + k] = hi;
    g_wTlb[col * 128 + k] = lo;
}

// ---------------- tensor-core GEMM via mma.sync bf16 (3-product split) ----------------
// C[M,256] = A[M,K] @ Wcat[K,256].  CTA 128x128, 8 warps (4M x 2N), warp tile 32x64.
// A pre-split bf16 hi/lo in global; staged per 32-K chunk via cp.async, 2-stage pipeline.
// Epilogue also emits: fp16 hs table (cols 0-127) and packed g_att (cols 192-195).

#define ASTRIDE 40
#define SSTAGE (128 * ASTRIDE)   // elems per (hi or lo) stage buffer

__device__ __forceinline__ void mma16816(float* c, const uint32_t* a, uint32_t b0, uint32_t b1) {
    asm volatile(
        "mma.sync.aligned.m16n8k16.row.col.f32.bf16.bf16.f32 "
        "{%0,%1,%2,%3}, {%4,%5,%6,%7}, {%8,%9}, {%0,%1,%2,%3};"
        : "+f"(c[0]), "+f"(c[1]), "+f"(c[2]), "+f"(c[3])
        : "r"(a[0]), "r"(a[1]), "r"(a[2]), "r"(a[3]), "r"(b0), "r"(b1));
}

__device__ __forceinline__ void cp16(uint32_t dst, const void* src, uint32_t sz) {
    asm volatile("cp.async.cg.shared.global [%0], [%1], 16, %2;"
                 :: "r"(dst), "l"(src), "r"(sz));
}

__global__ __launch_bounds__(256) void sgemm_mma_kernel(const uint16_t* __restrict__ Ah,
                                                        const uint16_t* __restrict__ Al,
                                                        int M, int K, int KP) {
    extern __shared__ uint16_t sm[];
    // layout: [stage0 AH][stage0 AL][stage1 AH][stage1 AL][BsH][BsL]
    uint16_t* BsH = sm + 4 * SSTAGE;
    uint16_t* BsL = BsH + 128 * KP;
    uint32_t sbase;
    asm("{ .reg .u64 t; cvta.to.shared.u64 t, %1; cvt.u32.u64 %0, t; }"
        : "=r"(sbase) : "l"(sm));

    int tid = threadIdx.x, lane = tid & 31, wid = tid >> 5;
    int bm0 = blockIdx.y * 128, n0 = blockIdx.x * 128;
    int wm = wid >> 1, wn = wid & 1;
    int lq = lane >> 2, lr = lane & 3;

    // stage B (entire K) once — plain loads, L2-resident
    int kq = K >> 2;
    for (int idx = tid; idx < 128 * kq; idx += 256) {
        int n = idx / kq, c = (idx % kq) * 4;
        uint2 h = *(const uint2*)&g_wThb[(n0 + n) * 128 + c];
        uint2 l = *(const uint2*)&g_wTlb[(n0 + n) * 128 + c];
        *(uint2*)&BsH[n * KP + c] = h;
        *(uint2*)&BsL[n * KP + c] = l;
    }

    float acc[2][8][4];
#pragma unroll
    for (int i = 0; i < 2; i++)
#pragma unroll
        for (int j = 0; j < 8; j++)
#pragma unroll
            for (int q = 0; q < 4; q++) acc[i][j][q] = 0.f;

    int nch = K >> 5;

    auto issue = [&](int ch) {
        int stg = ch & 1;
        int k0 = ch * 32;
        uint32_t baseH = sbase + (uint32_t)(2 * stg * SSTAGE) * 2u;
        uint32_t baseL = baseH + (uint32_t)SSTAGE * 2u;
#pragma unroll
        for (int it = 0; it < 2; it++) {
            int idx = tid + it * 256;           // 0..511: 16B groups
            int r = idx >> 2, g = idx & 3;      // row, 8-elem group
            int gr = bm0 + r;
            uint32_t sz = (gr < M) ? 16u : 0u;
            uint32_t doff = (uint32_t)(r * ASTRIDE + g * 8) * 2u;
            const uint16_t* sh = Ah + (size_t)gr * K + k0 + g * 8;
            const uint16_t* sl = Al + (size_t)gr * K + k0 + g * 8;
            cp16(baseH + doff, sh, sz);
            cp16(baseL + doff, sl, sz);
        }
        asm volatile("cp.async.commit_group;");
    };

    issue(0);
    for (int ch = 0; ch < nch; ch++) {
        if (ch + 1 < nch) issue(ch + 1);
        if (ch + 1 < nch) asm volatile("cp.async.wait_group 1;");
        else              asm volatile("cp.async.wait_group 0;");
        __syncthreads();
        int stg = ch & 1;
        uint16_t* AsH = sm + 2 * stg * SSTAGE;
        uint16_t* AsL = AsH + SSTAGE;
        int k0 = ch * 32;
#pragma unroll
        for (int ks = 0; ks < 2; ks++) {
            int kk = ks * 16;
            uint32_t ah[2][4], al[2][4];
#pragma unroll
            for (int i = 0; i < 2; i++) {
                int r = wm * 32 + i * 16 + lq;
                int base = r * ASTRIDE + kk + lr * 2;
                ah[i][0] = *(const uint32_t*)&AsH[base];
                ah[i][1] = *(const uint32_t*)&AsH[base + 8 * ASTRIDE];
                ah[i][2] = *(const uint32_t*)&AsH[base + 8];
                ah[i][3] = *(const uint32_t*)&AsH[base + 8 * ASTRIDE + 8];
                al[i][0] = *(const uint32_t*)&AsL[base];
                al[i][1] = *(const uint32_t*)&AsL[base + 8 * ASTRIDE];
                al[i][2] = *(const uint32_t*)&AsL[base + 8];
                al[i][3] = *(const uint32_t*)&AsL[base + 8 * ASTRIDE + 8];
            }
#pragma unroll
            for (int j = 0; j < 8; j++) {
                int n = wn * 64 + j * 8 + lq;
                int bb = n * KP + k0 + kk + lr * 2;
                uint32_t bh0 = *(const uint32_t*)&BsH[bb];
                uint32_t bh1 = *(const uint32_t*)&BsH[bb + 8];
                uint32_t bl0 = *(const uint32_t*)&BsL[bb];
                uint32_t bl1 = *(const uint32_t*)&BsL[bb + 8];
#pragma unroll
                for (int i = 0; i < 2; i++) {
                    mma16816(acc[i][j], ah[i], bh0, bh1);
                    mma16816(acc[i][j], al[i], bh0, bh1);
                    mma16816(acc[i][j], ah[i], bl0, bl1);
                }
            }
        }
        __syncthreads();
    }

    // epilogue: write fragments to g_tmp (+ fp16 hs table, + packed att)
    bool is_hs = (n0 == 0);
#pragma unroll
    for (int i = 0; i < 2; i++) {
        int r0 = bm0 + wm * 32 + i * 16 + lq;
        int r1 = r0 + 8;
#pragma unroll
        for (int j = 0; j < 8; j++) {
            int col = n0 + wn * 64 + j * 8 + lr * 2;
            if (r0 < M) {
                *(float2*)&g_tmp[r0 * ST + col] = make_float2(acc[i][j][0], acc[i][j][1]);
                if (is_hs)
                    *(__half2*)&g_hsh[r0 * 128 + col] = __floats2half2_rn(acc[i][j][0], acc[i][j][1]);
            }
            if (r1 < M) {
                *(float2*)&g_tmp[r1 * ST + col] = make_float2(acc[i][j][2], acc[i][j][3]);
                if (is_hs)
                    *(__half2*)&g_hsh[r1 * 128 + col] = __floats2half2_rn(acc[i][j][2], acc[i][j][3]);
            }
        }
        // packed attention pieces: cols 192-195 live in (n0=128, wn=1, j=0, lr<2)
        if (n0 == 128 && wn == 1 && lr < 2) {
            if (r0 < M) ((float2*)&g_att[r0])[lr] = make_float2(acc[i][0][0], acc[i][0][1]);
            if (r1 < M) ((float2*)&g_att[r1])[lr] = make_float2(acc[i][0][2], acc[i][0][3]);
        }
    }
}

// ---------------- per-destination attention + aggregation ----------------
// one warp per destination node; feature gather from fp16 hs table (256 B/edge)

__global__ __launch_bounds__(256) void gat_edge_kernel(const float* __restrict__ bAtt,
                                                       const float* __restrict__ bLin,
                                                       float* __restrict__ out,
                                                       int write_split) {
    int w = (blockIdx.x * blockDim.x + threadIdx.x) >> 5;
    int lane = threadIdx.x & 31;
    if (w >= NN) return;
    int beg = g_off[w], end = g_off[w + 1];
    int deg = end - beg;
    float4 aw = g_att[w];
    float ald0 = aw.z, ald1 = aw.w;
    const float2* als2 = (const float2*)g_att;   // als of node n at index 2*n

    // pass 1: per-head max of leaky-relu logits
    float m0 = -1e30f, m1 = -1e30f;
    for (int i = lane; i < deg; i += 32) {
        int s = g_srcs[beg + i];
        float2 a = als2[2 * s];
        float l0 = a.x + ald0;
        float l1 = a.y + ald1;
        l0 = l0 > 0.f ? l0 : 0.2f * l0;
        l1 = l1 > 0.f ? l1 : 0.2f * l1;
        m0 = fmaxf(m0, l0);
        m1 = fmaxf(m1, l1);
    }
#pragma unroll
    for (int o = 16; o > 0; o >>= 1) {
        m0 = fmaxf(m0, __shfl_xor_sync(0xffffffffu, m0, o));
        m1 = fmaxf(m1, __shfl_xor_sync(0xffffffffu, m1, o));
    }

    // pass 2: chunked exp + cooperative fp16 gather-accumulate
    float den0 = 0.f, den1 = 0.f;
    float4 acc = make_float4(0.f, 0.f, 0.f, 0.f);
    int h = lane >> 4;
    int col = lane * 4;
    for (int base = 0; base < deg; base += 32) {
        int i = base + lane;
        int s = 0;
        float w0 = 0.f, w1 = 0.f;
        if (i < deg) {
            s = g_srcs[beg + i];
            float2 a = als2[2 * s];
            float l0 = a.x + ald0;
            float l1 = a.y + ald1;
            l0 = l0 > 0.f ? l0 : 0.2f * l0;
            l1 = l1 > 0.f ? l1 : 0.2f * l1;
            w0 = __expf(l0 - m0);
            w1 = __expf(l1 - m1);
            den0 += w0;
            den1 += w1;
        }
        int nv = min(32, deg - base);
        for (int j = 0; j < nv; j++) {
            int sj = __shfl_sync(0xffffffffu, s, j);
            float wj0 = __shfl_sync(0xffffffffu, w0, j);
            float wj1 = __shfl_sync(0xffffffffu, w1, j);
            float wj = h ? wj1 : wj0;
            uint2 p = *(const uint2*)&g_hsh[sj * 128 + col];
            float2 f0 = __half22float2(*reinterpret_cast<__half2*>(&p.x));
            float2 f1 = __half22float2(*reinterpret_cast<__half2*>(&p.y));
            acc.x += wj * f0.x;
            acc.y += wj * f0.y;
            acc.z += wj * f1.x;
            acc.w += wj * f1.y;
        }
    }
#pragma unroll
    for (int o = 16; o > 0; o >>= 1) {
        den0 += __shfl_xor_sync(0xffffffffu, den0, o);
        den1 += __shfl_xor_sync(0xffffffffu, den1, o);
    }
    float inv0 = deg > 0 ? 1.f / den0 : 0.f;
    float inv1 = deg > 0 ? 1.f / den1 : 0.f;
    float invh = h ? inv1 : inv0;
    float sx = acc.x * invh, sy = acc.y * invh, sz = acc.z * invh, sw = acc.w * invh;
    float px = __shfl_xor_sync(0xffffffffu, sx, 16);
    float py = __shfl_xor_sync(0xffffffffu, sy, 16);
    float pz = __shfl_xor_sync(0xffffffffu, sz, 16);
    float pw = __shfl_xor_sync(0xffffffffu, sw, 16);
    if (lane < 16) {
        float4 skip = *(const float4*)&g_tmp[w * ST + 128 + col];
        float4 r;
        r.x = fmaxf(0.f, 0.5f * (sx + px) + bAtt[col + 0] + bLin[col + 0] + skip.x);
        r.y = fmaxf(0.f, 0.5f * (sy + py) + bAtt[col + 1] + bLin[col + 1] + skip.y);
        r.z = fmaxf(0.f, 0.5f * (sz + pz) + bAtt[col + 2] + bLin[col + 2] + skip.z);
        r.w = fmaxf(0.f, 0.5f * (sw + pw) + bAtt[col + 3] + bLin[col + 3] + skip.w);
        *(float4*)&out[w * 64 + col] = r;
        if (write_split) {
            uint16_t hh[4], ll[4];
            bf16_split(r.x, hh[0], ll[0]);
            bf16_split(r.y, hh[1], ll[1]);
            bf16_split(r.z, hh[2], ll[2]);
            bf16_split(r.w, hh[3], ll[3]);
            uint2 hp, lp;
            hp.x = (uint32_t)hh[0] | ((uint32_t)hh[1] << 16);
            hp.y = (uint32_t)hh[2] | ((uint32_t)hh[3] << 16);
            lp.x = (uint32_t)ll[0] | ((uint32_t)ll[1] << 16);
            lp.y = (uint32_t)ll[2] | ((uint32_t)ll[3] << 16);
            *(uint2*)&g_xh[w * 64 + col] = hp;
            *(uint2*)&g_xl[w * 64 + col] = lp;
        }
    }
}

// ---------------- launch ----------------

extern "C" void kernel_launch(void* const* d_in, const int* in_sizes, int n_in,
                              void* d_out, int out_size) {
    const float* x = (const float*)d_in[0];
    const int* ei = (const int*)d_in[1];
    const int* src = ei;
    const int* dst = ei + EE;
    const float* Ws[3] = {(const float*)d_in[2], (const float*)d_in[9], (const float*)d_in[16]};
    const float* Wd[3] = {(const float*)d_in[3], (const float*)d_in[10], (const float*)d_in[17]};
    const float* as_[3] = {(const float*)d_in[4], (const float*)d_in[11], (const float*)d_in[18]};
    const float* ad_[3] = {(const float*)d_in[5], (const float*)d_in[12], (const float*)d_in[19]};
    const float* b_[3] = {(const float*)d_in[6], (const float*)d_in[13], (const float*)d_in[20]};
    const float* Wl[3] = {(const float*)d_in[7], (const float*)d_in[14], (const float*)d_in[21]};
    const float* bl[3] = {(const float*)d_in[8], (const float*)d_in[15], (const float*)d_in[22]};
    float* out = (float*)d_out;

    float *h1, *h2;
    cudaGetSymbolAddress((void**)&h1, g_h1);
    cudaGetSymbolAddress((void**)&h2, g_h2);
    uint16_t *xh, *xl;
    cudaGetSymbolAddress((void**)&xh, g_xh);
    cudaGetSymbolAddress((void**)&xl, g_xl);

    // max dynamic smem (layer 1: KP = 136)
    int smem_max = (4 * SSTAGE + 2 * 128 * 136) * (int)sizeof(uint16_t);
    cudaFuncSetAttribute(sgemm_mma_kernel, cudaFuncAttributeMaxDynamicSharedMemorySize, smem_max);

    // CSR build (edge_index is identical across layers)
    zero_cnt_kernel<<<(NN + 255) / 256, 256>>>();
    count_kernel<<<(EE + 255) / 256, 256>>>(dst);
    scan_kernel<<<1, 1024>>>();
    fill_kernel<<<(EE + 255) / 256, 256>>>(src, dst);
    split_x_kernel<<<(NN * 32 + 255) / 256, 256>>>(x);

    int din = 128;
    for (int l = 0; l < 3; l++) {
        float* out_ptr = (l == 0) ? h1 : (l == 1 ? h2 : out);
        wcat_kernel<<<(din * 256 + 255) / 256, 256>>>(Ws[l], Wd[l], Wl[l], as_[l], ad_[l], din);
        int KP = din + 8;
        int smem = (4 * SSTAGE + 2 * 128 * KP) * (int)sizeof(uint16_t);
        dim3 g(2, (NN + 127) / 128);
        sgemm_mma_kernel<<<g, 256, smem>>>(xh, xl, NN, din, KP);
        gat_edge_kernel<<<(NN * 32 + 255) / 256, 256>>>(b_[l], bl[l], out_ptr, l < 2 ? 1 : 0);
        din = 64;
    }
}

// round 12
// speedup vs baseline: 1.4979x; 1.4979x over previous
#include <cuda_runtime.h>
#include <cuda_bf16.h>
#include <cstdint>

#define NN 50000
#define EE 800000
#define ST 256          // padded column stride of fused GEMM output
// tmp row layout: [0:128) hs (2 heads x 64), [128:192) skip = x@Wl,
//                 [192:194) als, [194:196) ald, [196:256) zero pad

__device__ __align__(128) float g_tmp[NN * ST];
__device__ __align__(128) float g_h1[NN * 64];
__device__ __align__(128) float g_h2[NN * 64];
__device__ __align__(128) float4 g_att[NN];            // {als0, als1, ald0, ald1}
__device__ __align__(128) uint16_t g_xh[NN * 128];     // layer input, bf16 hi
__device__ __align__(128) uint16_t g_xl[NN * 128];     // layer input, bf16 lo (residual)
__device__ __align__(128) uint16_t g_wThb[256 * 128];  // transposed fused weights, bf16 hi
__device__ __align__(128) uint16_t g_wTlb[256 * 128];  // transposed fused weights, bf16 lo
__device__ int g_off[NN + 1];
__device__ int g_cur[NN];
__device__ int g_srcs[EE];

// ---------------- CSR build (by destination) ----------------

__global__ void zero_cnt_kernel() {
    int i = blockIdx.x * blockDim.x + threadIdx.x;
    if (i < NN) g_cur[i] = 0;
}

__global__ void count_kernel(const int* __restrict__ dst) {
    int e = blockIdx.x * blockDim.x + threadIdx.x;
    if (e < EE) atomicAdd(&g_cur[dst[e]], 1);
}

__global__ void scan_kernel() {
    __shared__ int part[1024];
    int tid = threadIdx.x;
    const int CH = (NN + 1023) / 1024;
    int base = tid * CH;
    int s = 0;
    for (int j = 0; j < CH; j++) {
        int i = base + j;
        if (i < NN) s += g_cur[i];
    }
    part[tid] = s;
    __syncthreads();
    if (tid == 0) {
        int r = 0;
        for (int i = 0; i < 1024; i++) { int t = part[i]; part[i] = r; r += t; }
        g_off[NN] = r;
    }
    __syncthreads();
    int r = part[tid];
    for (int j = 0; j < CH; j++) {
        int i = base + j;
        if (i < NN) {
            int d = g_cur[i];
            g_off[i] = r;
            g_cur[i] = r;   // cursor for fill pass
            r += d;
        }
    }
}

__global__ void fill_kernel(const int* __restrict__ src, const int* __restrict__ dst) {
    int e = blockIdx.x * blockDim.x + threadIdx.x;
    if (e < EE) {
        int p = atomicAdd(&g_cur[dst[e]], 1);
        g_srcs[p] = src[e];
    }
}

// ---------------- bf16 split helpers ----------------

__device__ __forceinline__ void bf16_split(float v, uint16_t& hi, uint16_t& lo) {
    __nv_bfloat16 h = __float2bfloat16(v);
    float r = v - __bfloat162float(h);
    __nv_bfloat16 l = __float2bfloat16(r);
    hi = *reinterpret_cast<uint16_t*>(&h);
    lo = *reinterpret_cast<uint16_t*>(&l);
}

// split layer-1 input x [NN,128] into bf16 hi/lo
__global__ void split_x_kernel(const float* __restrict__ x) {
    int t = blockIdx.x * blockDim.x + threadIdx.x;
    if (t >= NN * 32) return;
    float4 v = *(const float4*)&x[t * 4];
    uint16_t h[4], l[4];
    bf16_split(v.x, h[0], l[0]);
    bf16_split(v.y, h[1], l[1]);
    bf16_split(v.z, h[2], l[2]);
    bf16_split(v.w, h[3], l[3]);
    uint2 hp, lp;
    hp.x = (uint32_t)h[0] | ((uint32_t)h[1] << 16);
    hp.y = (uint32_t)h[2] | ((uint32_t)h[3] << 16);
    lp.x = (uint32_t)l[0] | ((uint32_t)l[1] << 16);
    lp.y = (uint32_t)l[2] | ((uint32_t)l[3] << 16);
    *(uint2*)&g_xh[t * 4] = hp;
    *(uint2*)&g_xl[t * 4] = lp;
}

// pack attention logit pieces into hot float4 array
__global__ void att_pack_kernel() {
    int n = blockIdx.x * blockDim.x + threadIdx.x;
    if (n < NN) g_att[n] = *(const float4*)&g_tmp[n * ST + 192];
}

// ---------------- fused weight concat -> transposed bf16 hi/lo ----------------

__global__ void wcat_kernel(const float* __restrict__ Ws, const float* __restrict__ Wd,
                            const float* __restrict__ Wl, const float* __restrict__ as_,
                            const float* __restrict__ ad_, int din) {
    int t = blockIdx.x * blockDim.x + threadIdx.x;
    if (t >= din * 256) return;
    int k = t >> 8, col = t & 255;
    float v = 0.f;
    if (col < 128) {
        v = Ws[k * 128 + col];
    } else if (col < 192) {
        v = Wl[k * 64 + (col - 128)];
    } else if (col < 194) {
        int h = col - 192;
        float s = 0.f;
        for (int c = 0; c < 64; c++) s += Ws[k * 128 + h * 64 + c] * as_[h * 64 + c];
        v = s;
    } else if (col < 196) {
        int h = col - 194;
        float s = 0.f;
        for (int c = 0; c < 64; c++) s += Wd[k * 128 + h * 64 + c] * ad_[h * 64 + c];
        v = s;
    }
    uint16_t hi, lo;
    bf16_split(v, hi, lo);
    g_wThb[col * 128 + k] = hi;
    g_wTlb[col * 128 + k] = lo;
}

// ---------------- tensor-core GEMM via mma.sync bf16 (3-product split) ----------------
// C[M,256] = A[M,K] @ Wcat[K,256].  CTA 128x128, 8 warps (4M x 2N), warp tile 32x64.
// A pre-split bf16 hi/lo in global; staged per 32-K chunk via cp.async, 2-stage pipeline.

#define ASTRIDE 40
#define SSTAGE (128 * ASTRIDE)   // elems per (hi or lo) stage buffer

__device__ __forceinline__ void mma16816(float* c, const uint32_t* a, uint32_t b0, uint32_t b1) {
    asm volatile(
        "mma.sync.aligned.m16n8k16.row.col.f32.bf16.bf16.f32 "
        "{%0,%1,%2,%3}, {%4,%5,%6,%7}, {%8,%9}, {%0,%1,%2,%3};"
        : "+f"(c[0]), "+f"(c[1]), "+f"(c[2]), "+f"(c[3])
        : "r"(a[0]), "r"(a[1]), "r"(a[2]), "r"(a[3]), "r"(b0), "r"(b1));
}

__device__ __forceinline__ void cp16(uint32_t dst, const void* src, uint32_t sz) {
    asm volatile("cp.async.cg.shared.global [%0], [%1], 16, %2;"
                 :: "r"(dst), "l"(src), "r"(sz));
}

__global__ __launch_bounds__(256) void sgemm_mma_kernel(const uint16_t* __restrict__ Ah,
                                                        const uint16_t* __restrict__ Al,
                                                        int M, int K, int KP) {
    extern __shared__ uint16_t sm[];
    // layout: [stage0 AH][stage0 AL][stage1 AH][stage1 AL][BsH][BsL]
    uint16_t* BsH = sm + 4 * SSTAGE;
    uint16_t* BsL = BsH + 128 * KP;
    uint32_t sbase;
    asm("{ .reg .u64 t; cvta.to.shared.u64 t, %1; cvt.u32.u64 %0, t; }"
        : "=r"(sbase) : "l"(sm));

    int tid = threadIdx.x, lane = tid & 31, wid = tid >> 5;
    int bm0 = blockIdx.y * 128, n0 = blockIdx.x * 128;
    int wm = wid >> 1, wn = wid & 1;
    int lq = lane >> 2, lr = lane & 3;

    // stage B (entire K) once — plain loads, L2-resident
    int kq = K >> 2;
    for (int idx = tid; idx < 128 * kq; idx += 256) {
        int n = idx / kq, c = (idx % kq) * 4;
        uint2 h = *(const uint2*)&g_wThb[(n0 + n) * 128 + c];
        uint2 l = *(const uint2*)&g_wTlb[(n0 + n) * 128 + c];
        *(uint2*)&BsH[n * KP + c] = h;
        *(uint2*)&BsL[n * KP + c] = l;
    }

    float acc[2][8][4];
#pragma unroll
    for (int i = 0; i < 2; i++)
#pragma unroll
        for (int j = 0; j < 8; j++)
#pragma unroll
            for (int q = 0; q < 4; q++) acc[i][j][q] = 0.f;

    int nch = K >> 5;

    auto issue = [&](int ch) {
        int stg = ch & 1;
        int k0 = ch * 32;
        uint32_t baseH = sbase + (uint32_t)(2 * stg * SSTAGE) * 2u;
        uint32_t baseL = baseH + (uint32_t)SSTAGE * 2u;
#pragma unroll
        for (int it = 0; it < 2; it++) {
            int idx = tid + it * 256;           // 0..511: 16B groups
            int r = idx >> 2, g = idx & 3;      // row, 8-elem group
            int gr = bm0 + r;
            uint32_t sz = (gr < M) ? 16u : 0u;
            uint32_t doff = (uint32_t)(r * ASTRIDE + g * 8) * 2u;
            const uint16_t* sh = Ah + (size_t)gr * K + k0 + g * 8;
            const uint16_t* sl = Al + (size_t)gr * K + k0 + g * 8;
            cp16(baseH + doff, sh, sz);
            cp16(baseL + doff, sl, sz);
        }
        asm volatile("cp.async.commit_group;");
    };

    issue(0);
    for (int ch = 0; ch < nch; ch++) {
        if (ch + 1 < nch) issue(ch + 1);
        if (ch + 1 < nch) asm volatile("cp.async.wait_group 1;");
        else              asm volatile("cp.async.wait_group 0;");
        __syncthreads();
        int stg = ch & 1;
        uint16_t* AsH = sm + 2 * stg * SSTAGE;
        uint16_t* AsL = AsH + SSTAGE;
        int k0 = ch * 32;
#pragma unroll
        for (int ks = 0; ks < 2; ks++) {
            int kk = ks * 16;
            uint32_t ah[2][4], al[2][4];
#pragma unroll
            for (int i = 0; i < 2; i++) {
                int r = wm * 32 + i * 16 + lq;
                int base = r * ASTRIDE + kk + lr * 2;
                ah[i][0] = *(const uint32_t*)&AsH[base];
                ah[i][1] = *(const uint32_t*)&AsH[base + 8 * ASTRIDE];
                ah[i][2] = *(const uint32_t*)&AsH[base + 8];
                ah[i][3] = *(const uint32_t*)&AsH[base + 8 * ASTRIDE + 8];
                al[i][0] = *(const uint32_t*)&AsL[base];
                al[i][1] = *(const uint32_t*)&AsL[base + 8 * ASTRIDE];
                al[i][2] = *(const uint32_t*)&AsL[base + 8];
                al[i][3] = *(const uint32_t*)&AsL[base + 8 * ASTRIDE + 8];
            }
#pragma unroll
            for (int j = 0; j < 8; j++) {
                int n = wn * 64 + j * 8 + lq;
                int bb = n * KP + k0 + kk + lr * 2;
                uint32_t bh0 = *(const uint32_t*)&BsH[bb];
                uint32_t bh1 = *(const uint32_t*)&BsH[bb + 8];
                uint32_t bl0 = *(const uint32_t*)&BsL[bb];
                uint32_t bl1 = *(const uint32_t*)&BsL[bb + 8];
#pragma unroll
                for (int i = 0; i < 2; i++) {
                    mma16816(acc[i][j], ah[i], bh0, bh1);
                    mma16816(acc[i][j], al[i], bh0, bh1);
                    mma16816(acc[i][j], ah[i], bl0, bl1);
                }
            }
        }
        __syncthreads();
    }

    // epilogue: write fragments to g_tmp
#pragma unroll
    for (int i = 0; i < 2; i++) {
        int r0 = bm0 + wm * 32 + i * 16 + lq;
        int r1 = r0 + 8;
#pragma unroll
        for (int j = 0; j < 8; j++) {
            int col = n0 + wn * 64 + j * 8 + lr * 2;
            if (r0 < M) *(float2*)&g_tmp[r0 * ST + col] = make_float2(acc[i][j][0], acc[i][j][1]);
            if (r1 < M) *(float2*)&g_tmp[r1 * ST + col] = make_float2(acc[i][j][2], acc[i][j][3]);
        }
    }
}

// ---------------- per-destination attention + aggregation ----------------
// one warp per destination node. Softmax without max-subtraction (logits are
// O(1)-bounded: exp cannot overflow fp32; algebraically identical result).
// Gather loop processes 2 edges per iteration for MLP=2.

__global__ __launch_bounds__(256) void gat_edge_kernel(const float* __restrict__ bAtt,
                                                       const float* __restrict__ bLin,
                                                       float* __restrict__ out,
                                                       int write_split) {
    int w = (blockIdx.x * blockDim.x + threadIdx.x) >> 5;
    int lane = threadIdx.x & 31;
    if (w >= NN) return;
    int beg = g_off[w], end = g_off[w + 1];
    int deg = end - beg;
    float4 aw = g_att[w];
    float ald0 = aw.z, ald1 = aw.w;
    const float2* als2 = (const float2*)g_att;   // als of node n at index 2*n

    float den0 = 0.f, den1 = 0.f;
    float4 acc = make_float4(0.f, 0.f, 0.f, 0.f);
    int h = lane >> 4;        // head owned by this lane's feature slice
    int col = lane * 4;       // feature elements [col, col+4) of the 128-wide hs row
    for (int base = 0; base < deg; base += 32) {
        int i = base + lane;
        int s = 0;
        float w0 = 0.f, w1 = 0.f;
        if (i < deg) {
            s = g_srcs[beg + i];
            float2 a = als2[2 * s];
            float l0 = a.x + ald0;
            float l1 = a.y + ald1;
            l0 = l0 > 0.f ? l0 : 0.2f * l0;
            l1 = l1 > 0.f ? l1 : 0.2f * l1;
            w0 = __expf(l0);
            w1 = __expf(l1);
            den0 += w0;
            den1 += w1;
        }
        int nv = min(32, deg - base);
        int j = 0;
        for (; j + 2 <= nv; j += 2) {
            int sA = __shfl_sync(0xffffffffu, s, j);
            int sB = __shfl_sync(0xffffffffu, s, j + 1);
            float a0 = __shfl_sync(0xffffffffu, w0, j);
            float a1 = __shfl_sync(0xffffffffu, w1, j);
            float b0 = __shfl_sync(0xffffffffu, w0, j + 1);
            float b1 = __shfl_sync(0xffffffffu, w1, j + 1);
            const float4 vA = *(const float4*)&g_tmp[sA * ST + col];
            const float4 vB = *(const float4*)&g_tmp[sB * ST + col];
            float wA = h ? a1 : a0;
            float wB = h ? b1 : b0;
            acc.x = fmaf(wA, vA.x, acc.x);
            acc.y = fmaf(wA, vA.y, acc.y);
            acc.z = fmaf(wA, vA.z, acc.z);
            acc.w = fmaf(wA, vA.w, acc.w);
            acc.x = fmaf(wB, vB.x, acc.x);
            acc.y = fmaf(wB, vB.y, acc.y);
            acc.z = fmaf(wB, vB.z, acc.z);
            acc.w = fmaf(wB, vB.w, acc.w);
        }
        if (j < nv) {
            int sA = __shfl_sync(0xffffffffu, s, j);
            float a0 = __shfl_sync(0xffffffffu, w0, j);
            float a1 = __shfl_sync(0xffffffffu, w1, j);
            const float4 vA = *(const float4*)&g_tmp[sA * ST + col];
            float wA = h ? a1 : a0;
            acc.x = fmaf(wA, vA.x, acc.x);
            acc.y = fmaf(wA, vA.y, acc.y);
            acc.z = fmaf(wA, vA.z, acc.z);
            acc.w = fmaf(wA, vA.w, acc.w);
        }
    }
#pragma unroll
    for (int o = 16; o > 0; o >>= 1) {
        den0 += __shfl_xor_sync(0xffffffffu, den0, o);
        den1 += __shfl_xor_sync(0xffffffffu, den1, o);
    }
    float inv0 = deg > 0 ? 1.f / den0 : 0.f;
    float inv1 = deg > 0 ? 1.f / den1 : 0.f;
    float invh = h ? inv1 : inv0;
    float sx = acc.x * invh, sy = acc.y * invh, sz = acc.z * invh, sw = acc.w * invh;
    // combine heads: lanes 0..15 hold head0 elems [col,col+4), partner lane+16 holds head1
    float px = __shfl_xor_sync(0xffffffffu, sx, 16);
    float py = __shfl_xor_sync(0xffffffffu, sy, 16);
    float pz = __shfl_xor_sync(0xffffffffu, sz, 16);
    float pw = __shfl_xor_sync(0xffffffffu, sw, 16);
    if (lane < 16) {
        float4 skip = *(const float4*)&g_tmp[w * ST + 128 + col];
        float4 r;
        r.x = fmaxf(0.f, 0.5f * (sx + px) + bAtt[col + 0] + bLin[col + 0] + skip.x);
        r.y = fmaxf(0.f, 0.5f * (sy + py) + bAtt[col + 1] + bLin[col + 1] + skip.y);
        r.z = fmaxf(0.f, 0.5f * (sz + pz) + bAtt[col + 2] + bLin[col + 2] + skip.z);
        r.w = fmaxf(0.f, 0.5f * (sw + pw) + bAtt[col + 3] + bLin[col + 3] + skip.w);
        *(float4*)&out[w * 64 + col] = r;
        if (write_split) {
            uint16_t hh[4], ll[4];
            bf16_split(r.x, hh[0], ll[0]);
            bf16_split(r.y, hh[1], ll[1]);
            bf16_split(r.z, hh[2], ll[2]);
            bf16_split(r.w, hh[3], ll[3]);
            uint2 hp, lp;
            hp.x = (uint32_t)hh[0] | ((uint32_t)hh[1] << 16);
            hp.y = (uint32_t)hh[2] | ((uint32_t)hh[3] << 16);
            lp.x = (uint32_t)ll[0] | ((uint32_t)ll[1] << 16);
            lp.y = (uint32_t)ll[2] | ((uint32_t)ll[3] << 16);
            *(uint2*)&g_xh[w * 64 + col] = hp;
            *(uint2*)&g_xl[w * 64 + col] = lp;
        }
    }
}

// ---------------- launch ----------------

extern "C" void kernel_launch(void* const* d_in, const int* in_sizes, int n_in,
                              void* d_out, int out_size) {
    const float* x = (const float*)d_in[0];
    const int* ei = (const int*)d_in[1];
    const int* src = ei;
    const int* dst = ei + EE;
    const float* Ws[3] = {(const float*)d_in[2], (const float*)d_in[9], (const float*)d_in[16]};
    const float* Wd[3] = {(const float*)d_in[3], (const float*)d_in[10], (const float*)d_in[17]};
    const float* as_[3] = {(const float*)d_in[4], (const float*)d_in[11], (const float*)d_in[18]};
    const float* ad_[3] = {(const float*)d_in[5], (const float*)d_in[12], (const float*)d_in[19]};
    const float* b_[3] = {(const float*)d_in[6], (const float*)d_in[13], (const float*)d_in[20]};
    const float* Wl[3] = {(const float*)d_in[7], (const float*)d_in[14], (const float*)d_in[21]};
    const float* bl[3] = {(const float*)d_in[8], (const float*)d_in[15], (const float*)d_in[22]};
    float* out = (float*)d_out;

    float *h1, *h2;
    cudaGetSymbolAddress((void**)&h1, g_h1);
    cudaGetSymbolAddress((void**)&h2, g_h2);
    uint16_t *xh, *xl;
    cudaGetSymbolAddress((void**)&xh, g_xh);
    cudaGetSymbolAddress((void**)&xl, g_xl);

    // max dynamic smem (layer 1: KP = 136)
    int smem_max = (4 * SSTAGE + 2 * 128 * 136) * (int)sizeof(uint16_t);
    cudaFuncSetAttribute(sgemm_mma_kernel, cudaFuncAttributeMaxDynamicSharedMemorySize, smem_max);

    // CSR build (edge_index is identical across layers)
    zero_cnt_kernel<<<(NN + 255) / 256, 256>>>();
    count_kernel<<<(EE + 255) / 256, 256>>>(dst);
    scan_kernel<<<1, 1024>>>();
    fill_kernel<<<(EE + 255) / 256, 256>>>(src, dst);
    split_x_kernel<<<(NN * 32 + 255) / 256, 256>>>(x);

    int din = 128;
    for (int l = 0; l < 3; l++) {
        float* out_ptr = (l == 0) ? h1 : (l == 1 ? h2 : out);
        wcat_kernel<<<(din * 256 + 255) / 256, 256>>>(Ws[l], Wd[l], Wl[l], as_[l], ad_[l], din);
        int KP = din + 8;
        int smem = (4 * SSTAGE + 2 * 128 * KP) * (int)sizeof(uint16_t);
        dim3 g(2, (NN + 127) / 128);
        sgemm_mma_kernel<<<g, 256, smem>>>(xh, xl, NN, din, KP);
        att_pack_kernel<<<(NN + 255) / 256, 256>>>();
        gat_edge_kernel<<<(NN * 32 + 255) / 256, 256>>>(b_[l], bl[l], out_ptr, l < 2 ? 1 : 0);
        din = 64;
    }
}

// round 13
// speedup vs baseline: 1.6694x; 1.1145x over previous
#include <cuda_runtime.h>
#include <cuda_bf16.h>
#include <cstdint>

#define NN 50000
#define EE 800000
#define ST 256          // padded column stride of fused GEMM output
// tmp row layout: [0:128) hs (2 heads x 64), [128:192) skip = x@Wl,
//                 [192:194) als, [194:196) ald, [196:256) zero pad

__device__ __align__(128) float g_tmp[NN * ST];
__device__ __align__(128) float g_h1[NN * 64];
__device__ __align__(128) float g_h2[NN * 64];
__device__ __align__(128) float4 g_att[NN];            // {als0, als1, ald0, ald1}
__device__ __align__(128) float2 g_ew[EE];             // per-edge softmax weights (CSR order)
__device__ __align__(128) uint16_t g_xh[NN * 128];     // layer input, bf16 hi
__device__ __align__(128) uint16_t g_xl[NN * 128];     // layer input, bf16 lo (residual)
__device__ __align__(128) uint16_t g_wThb[256 * 128];  // transposed fused weights, bf16 hi
__device__ __align__(128) uint16_t g_wTlb[256 * 128];  // transposed fused weights, bf16 lo
__device__ int g_off[NN + 1];
__device__ int g_cur[NN];
__device__ int g_srcs[EE];
__device__ int g_pos[EE];                              // original edge -> CSR slot

// ---------------- CSR build (by destination) ----------------

__global__ void zero_cnt_kernel() {
    int i = blockIdx.x * blockDim.x + threadIdx.x;
    if (i < NN) g_cur[i] = 0;
}

__global__ void count_kernel(const int* __restrict__ dst) {
    int e = blockIdx.x * blockDim.x + threadIdx.x;
    if (e < EE) atomicAdd(&g_cur[dst[e]], 1);
}

__global__ void scan_kernel() {
    __shared__ int part[1024];
    int tid = threadIdx.x;
    const int CH = (NN + 1023) / 1024;
    int base = tid * CH;
    int s = 0;
    for (int j = 0; j < CH; j++) {
        int i = base + j;
        if (i < NN) s += g_cur[i];
    }
    part[tid] = s;
    __syncthreads();
    if (tid == 0) {
        int r = 0;
        for (int i = 0; i < 1024; i++) { int t = part[i]; part[i] = r; r += t; }
        g_off[NN] = r;
    }
    __syncthreads();
    int r = part[tid];
    for (int j = 0; j < CH; j++) {
        int i = base + j;
        if (i < NN) {
            int d = g_cur[i];
            g_off[i] = r;
            g_cur[i] = r;   // cursor for fill pass
            r += d;
        }
    }
}

__global__ void fill_kernel(const int* __restrict__ src, const int* __restrict__ dst) {
    int e = blockIdx.x * blockDim.x + threadIdx.x;
    if (e < EE) {
        int p = atomicAdd(&g_cur[dst[e]], 1);
        g_srcs[p] = src[e];
        g_pos[e] = p;
    }
}

// ---------------- bf16 split helpers ----------------

__device__ __forceinline__ void bf16_split(float v, uint16_t& hi, uint16_t& lo) {
    __nv_bfloat16 h = __float2bfloat16(v);
    float r = v - __bfloat162float(h);
    __nv_bfloat16 l = __float2bfloat16(r);
    hi = *reinterpret_cast<uint16_t*>(&h);
    lo = *reinterpret_cast<uint16_t*>(&l);
}

// split layer-1 input x [NN,128] into bf16 hi/lo
__global__ void split_x_kernel(const float* __restrict__ x) {
    int t = blockIdx.x * blockDim.x + threadIdx.x;
    if (t >= NN * 32) return;
    float4 v = *(const float4*)&x[t * 4];
    uint16_t h[4], l[4];
    bf16_split(v.x, h[0], l[0]);
    bf16_split(v.y, h[1], l[1]);
    bf16_split(v.z, h[2], l[2]);
    bf16_split(v.w, h[3], l[3]);
    uint2 hp, lp;
    hp.x = (uint32_t)h[0] | ((uint32_t)h[1] << 16);
    hp.y = (uint32_t)h[2] | ((uint32_t)h[3] << 16);
    lp.x = (uint32_t)l[0] | ((uint32_t)l[1] << 16);
    lp.y = (uint32_t)l[2] | ((uint32_t)l[3] << 16);
    *(uint2*)&g_xh[t * 4] = hp;
    *(uint2*)&g_xl[t * 4] = lp;
}

// pack attention logit pieces into hot float4 array
__global__ void att_pack_kernel() {
    int n = blockIdx.x * blockDim.x + threadIdx.x;
    if (n < NN) g_att[n] = *(const float4*)&g_tmp[n * ST + 192];
}

// per-edge softmax weights (edge-parallel, written to CSR slots).
// no max-subtraction: logits are O(1)-bounded, exp cannot overflow fp32.
__global__ void ew_kernel(const int* __restrict__ src, const int* __restrict__ dst) {
    int e = blockIdx.x * blockDim.x + threadIdx.x;
    if (e >= EE) return;
    float4 as_ = g_att[src[e]];
    float4 ad_ = g_att[dst[e]];
    float l0 = as_.x + ad_.z;
    float l1 = as_.y + ad_.w;
    l0 = l0 > 0.f ? l0 : 0.2f * l0;
    l1 = l1 > 0.f ? l1 : 0.2f * l1;
    g_ew[g_pos[e]] = make_float2(__expf(l0), __expf(l1));
}

// ---------------- fused weight concat -> transposed bf16 hi/lo ----------------

__global__ void wcat_kernel(const float* __restrict__ Ws, const float* __restrict__ Wd,
                            const float* __restrict__ Wl, const float* __restrict__ as_,
                            const float* __restrict__ ad_, int din) {
    int t = blockIdx.x * blockDim.x + threadIdx.x;
    if (t >= din * 256) return;
    int k = t >> 8, col = t & 255;
    float v = 0.f;
    if (col < 128) {
        v = Ws[k * 128 + col];
    } else if (col < 192) {
        v = Wl[k * 64 + (col - 128)];
    } else if (col < 194) {
        int h = col - 192;
        float s = 0.f;
        for (int c = 0; c < 64; c++) s += Ws[k * 128 + h * 64 + c] * as_[h * 64 + c];
        v = s;
    } else if (col < 196) {
        int h = col - 194;
        float s = 0.f;
        for (int c = 0; c < 64; c++) s += Wd[k * 128 + h * 64 + c] * ad_[h * 64 + c];
        v = s;
    }
    uint16_t hi, lo;
    bf16_split(v, hi, lo);
    g_wThb[col * 128 + k] = hi;
    g_wTlb[col * 128 + k] = lo;
}

// ---------------- tensor-core GEMM via mma.sync bf16 (3-product split) ----------------
// C[M,256] = A[M,K] @ Wcat[K,256].  CTA 128x128, 8 warps (4M x 2N), warp tile 32x64.
// A pre-split bf16 hi/lo in global; staged per 32-K chunk via cp.async, 2-stage pipeline.

#define ASTRIDE 40
#define SSTAGE (128 * ASTRIDE)   // elems per (hi or lo) stage buffer

__device__ __forceinline__ void mma16816(float* c, const uint32_t* a, uint32_t b0, uint32_t b1) {
    asm volatile(
        "mma.sync.aligned.m16n8k16.row.col.f32.bf16.bf16.f32 "
        "{%0,%1,%2,%3}, {%4,%5,%6,%7}, {%8,%9}, {%0,%1,%2,%3};"
        : "+f"(c[0]), "+f"(c[1]), "+f"(c[2]), "+f"(c[3])
        : "r"(a[0]), "r"(a[1]), "r"(a[2]), "r"(a[3]), "r"(b0), "r"(b1));
}

__device__ __forceinline__ void cp16(uint32_t dst, const void* src, uint32_t sz) {
    asm volatile("cp.async.cg.shared.global [%0], [%1], 16, %2;"
                 :: "r"(dst), "l"(src), "r"(sz));
}

__global__ __launch_bounds__(256) void sgemm_mma_kernel(const uint16_t* __restrict__ Ah,
                                                        const uint16_t* __restrict__ Al,
                                                        int M, int K, int KP) {
    extern __shared__ uint16_t sm[];
    // layout: [stage0 AH][stage0 AL][stage1 AH][stage1 AL][BsH][BsL]
    uint16_t* BsH = sm + 4 * SSTAGE;
    uint16_t* BsL = BsH + 128 * KP;
    uint32_t sbase;
    asm("{ .reg .u64 t; cvta.to.shared.u64 t, %1; cvt.u32.u64 %0, t; }"
        : "=r"(sbase) : "l"(sm));

    int tid = threadIdx.x, lane = tid & 31, wid = tid >> 5;
    int bm0 = blockIdx.y * 128, n0 = blockIdx.x * 128;
    int wm = wid >> 1, wn = wid & 1;
    int lq = lane >> 2, lr = lane & 3;

    // stage B (entire K) once — plain loads, L2-resident
    int kq = K >> 2;
    for (int idx = tid; idx < 128 * kq; idx += 256) {
        int n = idx / kq, c = (idx % kq) * 4;
        uint2 h = *(const uint2*)&g_wThb[(n0 + n) * 128 + c];
        uint2 l = *(const uint2*)&g_wTlb[(n0 + n) * 128 + c];
        *(uint2*)&BsH[n * KP + c] = h;
        *(uint2*)&BsL[n * KP + c] = l;
    }

    float acc[2][8][4];
#pragma unroll
    for (int i = 0; i < 2; i++)
#pragma unroll
        for (int j = 0; j < 8; j++)
#pragma unroll
            for (int q = 0; q < 4; q++) acc[i][j][q] = 0.f;

    int nch = K >> 5;

    auto issue = [&](int ch) {
        int stg = ch & 1;
        int k0 = ch * 32;
        uint32_t baseH = sbase + (uint32_t)(2 * stg * SSTAGE) * 2u;
        uint32_t baseL = baseH + (uint32_t)SSTAGE * 2u;
#pragma unroll
        for (int it = 0; it < 2; it++) {
            int idx = tid + it * 256;           // 0..511: 16B groups
            int r = idx >> 2, g = idx & 3;      // row, 8-elem group
            int gr = bm0 + r;
            uint32_t sz = (gr < M) ? 16u : 0u;
            uint32_t doff = (uint32_t)(r * ASTRIDE + g * 8) * 2u;
            const uint16_t* sh = Ah + (size_t)gr * K + k0 + g * 8;
            const uint16_t* sl = Al + (size_t)gr * K + k0 + g * 8;
            cp16(baseH + doff, sh, sz);
            cp16(baseL + doff, sl, sz);
        }
        asm volatile("cp.async.commit_group;");
    };

    issue(0);
    for (int ch = 0; ch < nch; ch++) {
        if (ch + 1 < nch) issue(ch + 1);
        if (ch + 1 < nch) asm volatile("cp.async.wait_group 1;");
        else              asm volatile("cp.async.wait_group 0;");
        __syncthreads();
        int stg = ch & 1;
        uint16_t* AsH = sm + 2 * stg * SSTAGE;
        uint16_t* AsL = AsH + SSTAGE;
        int k0 = ch * 32;
#pragma unroll
        for (int ks = 0; ks < 2; ks++) {
            int kk = ks * 16;
            uint32_t ah[2][4], al[2][4];
#pragma unroll
            for (int i = 0; i < 2; i++) {
                int r = wm * 32 + i * 16 + lq;
                int base = r * ASTRIDE + kk + lr * 2;
                ah[i][0] = *(const uint32_t*)&AsH[base];
                ah[i][1] = *(const uint32_t*)&AsH[base + 8 * ASTRIDE];
                ah[i][2] = *(const uint32_t*)&AsH[base + 8];
                ah[i][3] = *(const uint32_t*)&AsH[base + 8 * ASTRIDE + 8];
                al[i][0] = *(const uint32_t*)&AsL[base];
                al[i][1] = *(const uint32_t*)&AsL[base + 8 * ASTRIDE];
                al[i][2] = *(const uint32_t*)&AsL[base + 8];
                al[i][3] = *(const uint32_t*)&AsL[base + 8 * ASTRIDE + 8];
            }
#pragma unroll
            for (int j = 0; j < 8; j++) {
                int n = wn * 64 + j * 8 + lq;
                int bb = n * KP + k0 + kk + lr * 2;
                uint32_t bh0 = *(const uint32_t*)&BsH[bb];
                uint32_t bh1 = *(const uint32_t*)&BsH[bb + 8];
                uint32_t bl0 = *(const uint32_t*)&BsL[bb];
                uint32_t bl1 = *(const uint32_t*)&BsL[bb + 8];
#pragma unroll
                for (int i = 0; i < 2; i++) {
                    mma16816(acc[i][j], ah[i], bh0, bh1);
                    mma16816(acc[i][j], al[i], bh0, bh1);
                    mma16816(acc[i][j], ah[i], bl0, bl1);
                }
            }
        }
        __syncthreads();
    }

    // epilogue: write fragments to g_tmp
#pragma unroll
    for (int i = 0; i < 2; i++) {
        int r0 = bm0 + wm * 32 + i * 16 + lq;
        int r1 = r0 + 8;
#pragma unroll
        for (int j = 0; j < 8; j++) {
            int col = n0 + wn * 64 + j * 8 + lr * 2;
            if (r0 < M) *(float2*)&g_tmp[r0 * ST + col] = make_float2(acc[i][j][0], acc[i][j][1]);
            if (r1 < M) *(float2*)&g_tmp[r1 * ST + col] = make_float2(acc[i][j][2], acc[i][j][3]);
        }
    }
}

// ---------------- per-destination aggregation ----------------
// one warp per destination node; per-edge weights precomputed in g_ew.
// all per-edge metadata read via uniform broadcast loads (no shfl).

__global__ __launch_bounds__(256) void gat_edge_kernel(const float* __restrict__ bAtt,
                                                       const float* __restrict__ bLin,
                                                       float* __restrict__ out,
                                                       int write_split) {
    int w = (blockIdx.x * blockDim.x + threadIdx.x) >> 5;
    int lane = threadIdx.x & 31;
    if (w >= NN) return;
    int beg = g_off[w], end = g_off[w + 1];
    int deg = end - beg;

    float den0 = 0.f, den1 = 0.f;
    float4 acc = make_float4(0.f, 0.f, 0.f, 0.f);
    int h = lane >> 4;        // head owned by this lane's feature slice
    int col = lane * 4;       // feature elements [col, col+4) of the 128-wide hs row
    int j = beg;
    for (; j + 2 <= end; j += 2) {
        int sA = __ldg(&g_srcs[j]);
        int sB = __ldg(&g_srcs[j + 1]);
        float2 wpA = __ldg(&g_ew[j]);
        float2 wpB = __ldg(&g_ew[j + 1]);
        const float4 vA = *(const float4*)&g_tmp[sA * ST + col];
        const float4 vB = *(const float4*)&g_tmp[sB * ST + col];
        den0 += wpA.x + wpB.x;
        den1 += wpA.y + wpB.y;
        float wA = h ? wpA.y : wpA.x;
        float wB = h ? wpB.y : wpB.x;
        acc.x = fmaf(wA, vA.x, acc.x);
        acc.y = fmaf(wA, vA.y, acc.y);
        acc.z = fmaf(wA, vA.z, acc.z);
        acc.w = fmaf(wA, vA.w, acc.w);
        acc.x = fmaf(wB, vB.x, acc.x);
        acc.y = fmaf(wB, vB.y, acc.y);
        acc.z = fmaf(wB, vB.z, acc.z);
        acc.w = fmaf(wB, vB.w, acc.w);
    }
    if (j < end) {
        int sA = __ldg(&g_srcs[j]);
        float2 wpA = __ldg(&g_ew[j]);
        const float4 vA = *(const float4*)&g_tmp[sA * ST + col];
        den0 += wpA.x;
        den1 += wpA.y;
        float wA = h ? wpA.y : wpA.x;
        acc.x = fmaf(wA, vA.x, acc.x);
        acc.y = fmaf(wA, vA.y, acc.y);
        acc.z = fmaf(wA, vA.z, acc.z);
        acc.w = fmaf(wA, vA.w, acc.w);
    }
    float inv0 = deg > 0 ? 1.f / den0 : 0.f;
    float inv1 = deg > 0 ? 1.f / den1 : 0.f;
    float invh = h ? inv1 : inv0;
    float sx = acc.x * invh, sy = acc.y * invh, sz = acc.z * invh, sw = acc.w * invh;
    // combine heads: lanes 0..15 hold head0 elems [col,col+4), partner lane+16 holds head1
    float px = __shfl_xor_sync(0xffffffffu, sx, 16);
    float py = __shfl_xor_sync(0xffffffffu, sy, 16);
    float pz = __shfl_xor_sync(0xffffffffu, sz, 16);
    float pw = __shfl_xor_sync(0xffffffffu, sw, 16);
    if (lane < 16) {
        float4 skip = *(const float4*)&g_tmp[w * ST + 128 + col];
        float4 r;
        r.x = fmaxf(0.f, 0.5f * (sx + px) + bAtt[col + 0] + bLin[col + 0] + skip.x);
        r.y = fmaxf(0.f, 0.5f * (sy + py) + bAtt[col + 1] + bLin[col + 1] + skip.y);
        r.z = fmaxf(0.f, 0.5f * (sz + pz) + bAtt[col + 2] + bLin[col + 2] + skip.z);
        r.w = fmaxf(0.f, 0.5f * (sw + pw) + bAtt[col + 3] + bLin[col + 3] + skip.w);
        *(float4*)&out[w * 64 + col] = r;
        if (write_split) {
            uint16_t hh[4], ll[4];
            bf16_split(r.x, hh[0], ll[0]);
            bf16_split(r.y, hh[1], ll[1]);
            bf16_split(r.z, hh[2], ll[2]);
            bf16_split(r.w, hh[3], ll[3]);
            uint2 hp, lp;
            hp.x = (uint32_t)hh[0] | ((uint32_t)hh[1] << 16);
            hp.y = (uint32_t)hh[2] | ((uint32_t)hh[3] << 16);
            lp.x = (uint32_t)ll[0] | ((uint32_t)ll[1] << 16);
            lp.y = (uint32_t)ll[2] | ((uint32_t)ll[3] << 16);
            *(uint2*)&g_xh[w * 64 + col] = hp;
            *(uint2*)&g_xl[w * 64 + col] = lp;
        }
    }
}

// ---------------- launch ----------------

extern "C" void kernel_launch(void* const* d_in, const int* in_sizes, int n_in,
                              void* d_out, int out_size) {
    const float* x = (const float*)d_in[0];
    const int* ei = (const int*)d_in[1];
    const int* src = ei;
    const int* dst = ei + EE;
    const float* Ws[3] = {(const float*)d_in[2], (const float*)d_in[9], (const float*)d_in[16]};
    const float* Wd[3] = {(const float*)d_in[3], (const float*)d_in[10], (const float*)d_in[17]};
    const float* as_[3] = {(const float*)d_in[4], (const float*)d_in[11], (const float*)d_in[18]};
    const float* ad_[3] = {(const float*)d_in[5], (const float*)d_in[12], (const float*)d_in[19]};
    const float* b_[3] = {(const float*)d_in[6], (const float*)d_in[13], (const float*)d_in[20]};
    const float* Wl[3] = {(const float*)d_in[7], (const float*)d_in[14], (const float*)d_in[21]};
    const float* bl[3] = {(const float*)d_in[8], (const float*)d_in[15], (const float*)d_in[22]};
    float* out = (float*)d_out;

    float *h1, *h2;
    cudaGetSymbolAddress((void**)&h1, g_h1);
    cudaGetSymbolAddress((void**)&h2, g_h2);
    uint16_t *xh, *xl;
    cudaGetSymbolAddress((void**)&xh, g_xh);
    cudaGetSymbolAddress((void**)&xl, g_xl);

    // side stream + fork/join events (created once; capture-safe fork-join pattern)
    static cudaStream_t s1 = [] {
        cudaStream_t s;
        cudaStreamCreateWithFlags(&s, cudaStreamNonBlocking);
        return s;
    }();
    static cudaEvent_t evFork = [] {
        cudaEvent_t e;
        cudaEventCreateWithFlags(&e, cudaEventDisableTiming);
        return e;
    }();
    static cudaEvent_t evJoin = [] {
        cudaEvent_t e;
        cudaEventCreateWithFlags(&e, cudaEventDisableTiming);
        return e;
    }();

    // max dynamic smem (layer 1: KP = 136)
    int smem_max = (4 * SSTAGE + 2 * 128 * 136) * (int)sizeof(uint16_t);
    cudaFuncSetAttribute(sgemm_mma_kernel, cudaFuncAttributeMaxDynamicSharedMemorySize, smem_max);

    // fork: CSR build on side stream, overlapped with layer-1 dense chain
    cudaEventRecord(evFork, 0);
    cudaStreamWaitEvent(s1, evFork, 0);
    zero_cnt_kernel<<<(NN + 255) / 256, 256, 0, s1>>>();
    count_kernel<<<(EE + 255) / 256, 256, 0, s1>>>(dst);
    scan_kernel<<<1, 1024, 0, s1>>>();
    fill_kernel<<<(EE + 255) / 256, 256, 0, s1>>>(src, dst);
    cudaEventRecord(evJoin, s1);

    // main stream: layer-1 dense chain
    split_x_kernel<<<(NN * 32 + 255) / 256, 256>>>(x);

    int din = 128;
    for (int l = 0; l < 3; l++) {
        float* out_ptr = (l == 0) ? h1 : (l == 1 ? h2 : out);
        wcat_kernel<<<(din * 256 + 255) / 256, 256>>>(Ws[l], Wd[l], Wl[l], as_[l], ad_[l], din);
        int KP = din + 8;
        int smem = (4 * SSTAGE + 2 * 128 * KP) * (int)sizeof(uint16_t);
        dim3 g(2, (NN + 127) / 128);
        sgemm_mma_kernel<<<g, 256, smem>>>(xh, xl, NN, din, KP);
        att_pack_kernel<<<(NN + 255) / 256, 256>>>();
        if (l == 0) cudaStreamWaitEvent(0, evJoin, 0);   // join: ew needs g_pos/g_srcs
        ew_kernel<<<(EE + 255) / 256, 256>>>(src, dst);
        gat_edge_kernel<<<(NN * 32 + 255) / 256, 256>>>(b_[l], bl[l], out_ptr, l < 2 ? 1 : 0);
        din = 64;
    }
}

// round 14
// speedup vs baseline: 1.7168x; 1.0284x over previous
#include <cuda_runtime.h>
#include <cuda_bf16.h>
#include <cstdint>

#define NN 50000
#define EE 800000
#define ST 256          // padded column stride of fused GEMM output
// tmp row layout: [0:128) hs (2 heads x 64), [128:192) skip = x@Wl,
//                 [192:194) als, [194:196) ald, [196:256) zero pad

__device__ __align__(128) float g_tmp[NN * ST];
__device__ __align__(128) float g_h1[NN * 64];
__device__ __align__(128) float g_h2[NN * 64];
__device__ __align__(128) float4 g_att[NN];            // {als0, als1, ald0, ald1}
__device__ __align__(128) float4 g_ew4[EE];            // {w0, w1, bitcast(src), 0} CSR order
__device__ __align__(128) uint16_t g_xh[NN * 128];     // layer input, bf16 hi
__device__ __align__(128) uint16_t g_xl[NN * 128];     // layer input, bf16 lo (residual)
__device__ __align__(128) uint16_t g_wThb[3][256 * 128];  // per-layer fused weights, bf16 hi
__device__ __align__(128) uint16_t g_wTlb[3][256 * 128];  // per-layer fused weights, bf16 lo
__device__ int g_off[NN + 1];
__device__ int g_cur[NN];
__device__ int g_pos[EE];                              // original edge -> CSR slot

// ---------------- CSR build (by destination) ----------------

__global__ void zero_cnt_kernel() {
    int i = blockIdx.x * blockDim.x + threadIdx.x;
    if (i < NN) g_cur[i] = 0;
}

__global__ void count_kernel(const int* __restrict__ dst) {
    int e = blockIdx.x * blockDim.x + threadIdx.x;
    if (e < EE) atomicAdd(&g_cur[dst[e]], 1);
}

__global__ void scan_kernel() {
    __shared__ int part[1024];
    int tid = threadIdx.x;
    const int CH = (NN + 1023) / 1024;
    int base = tid * CH;
    int s = 0;
    for (int j = 0; j < CH; j++) {
        int i = base + j;
        if (i < NN) s += g_cur[i];
    }
    part[tid] = s;
    __syncthreads();
    if (tid == 0) {
        int r = 0;
        for (int i = 0; i < 1024; i++) { int t = part[i]; part[i] = r; r += t; }
        g_off[NN] = r;
    }
    __syncthreads();
    int r = part[tid];
    for (int j = 0; j < CH; j++) {
        int i = base + j;
        if (i < NN) {
            int d = g_cur[i];
            g_off[i] = r;
            g_cur[i] = r;   // cursor for fill pass
            r += d;
        }
    }
}

__global__ void fill_kernel(const int* __restrict__ dst) {
    int e = blockIdx.x * blockDim.x + threadIdx.x;
    if (e < EE) g_pos[e] = atomicAdd(&g_cur[dst[e]], 1);
}

// ---------------- bf16 split helpers ----------------

__device__ __forceinline__ void bf16_split(float v, uint16_t& hi, uint16_t& lo) {
    __nv_bfloat16 h = __float2bfloat16(v);
    float r = v - __bfloat162float(h);
    __nv_bfloat16 l = __float2bfloat16(r);
    hi = *reinterpret_cast<uint16_t*>(&h);
    lo = *reinterpret_cast<uint16_t*>(&l);
}

// split layer-1 input x [NN,128] into bf16 hi/lo
__global__ void split_x_kernel(const float* __restrict__ x) {
    int t = blockIdx.x * blockDim.x + threadIdx.x;
    if (t >= NN * 32) return;
    float4 v = *(const float4*)&x[t * 4];
    uint16_t h[4], l[4];
    bf16_split(v.x, h[0], l[0]);
    bf16_split(v.y, h[1], l[1]);
    bf16_split(v.z, h[2], l[2]);
    bf16_split(v.w, h[3], l[3]);
    uint2 hp, lp;
    hp.x = (uint32_t)h[0] | ((uint32_t)h[1] << 16);
    hp.y = (uint32_t)h[2] | ((uint32_t)h[3] << 16);
    lp.x = (uint32_t)l[0] | ((uint32_t)l[1] << 16);
    lp.y = (uint32_t)l[2] | ((uint32_t)l[3] << 16);
    *(uint2*)&g_xh[t * 4] = hp;
    *(uint2*)&g_xl[t * 4] = lp;
}

// per-edge softmax weights + packed src (edge-parallel, written to CSR slots).
// no max-subtraction: logits are O(1)-bounded, exp cannot overflow fp32.
__global__ void ew_kernel(const int* __restrict__ src, const int* __restrict__ dst) {
    int e = blockIdx.x * blockDim.x + threadIdx.x;
    if (e >= EE) return;
    int s = src[e];
    float4 as_ = g_att[s];
    float4 ad_ = g_att[dst[e]];
    float l0 = as_.x + ad_.z;
    float l1 = as_.y + ad_.w;
    l0 = l0 > 0.f ? l0 : 0.2f * l0;
    l1 = l1 > 0.f ? l1 : 0.2f * l1;
    g_ew4[g_pos[e]] = make_float4(__expf(l0), __expf(l1), __int_as_float(s), 0.f);
}

// ---------------- fused weight concat -> transposed bf16 hi/lo ----------------

__global__ void wcat_kernel(const float* __restrict__ Ws, const float* __restrict__ Wd,
                            const float* __restrict__ Wl, const float* __restrict__ as_,
                            const float* __restrict__ ad_, int din,
                            uint16_t* __restrict__ outH, uint16_t* __restrict__ outL) {
    int t = blockIdx.x * blockDim.x + threadIdx.x;
    if (t >= din * 256) return;
    int k = t >> 8, col = t & 255;
    float v = 0.f;
    if (col < 128) {
        v = Ws[k * 128 + col];
    } else if (col < 192) {
        v = Wl[k * 64 + (col - 128)];
    } else if (col < 194) {
        int h = col - 192;
        float s = 0.f;
        for (int c = 0; c < 64; c++) s += Ws[k * 128 + h * 64 + c] * as_[h * 64 + c];
        v = s;
    } else if (col < 196) {
        int h = col - 194;
        float s = 0.f;
        for (int c = 0; c < 64; c++) s += Wd[k * 128 + h * 64 + c] * ad_[h * 64 + c];
        v = s;
    }
    uint16_t hi, lo;
    bf16_split(v, hi, lo);
    outH[col * 128 + k] = hi;
    outL[col * 128 + k] = lo;
}

// ---------------- tensor-core GEMM via mma.sync bf16 (3-product split) ----------------
// C[M,256] = A[M,K] @ Wcat[K,256].  CTA 128x128, 8 warps (4M x 2N), warp tile 32x64.
// A pre-split bf16 hi/lo in global; staged per 32-K chunk via cp.async, 2-stage pipeline.
// Epilogue also writes packed g_att (cols 192-195, CTA n0=128).

#define ASTRIDE 40
#define SSTAGE (128 * ASTRIDE)   // elems per (hi or lo) stage buffer

__device__ __forceinline__ void mma16816(float* c, const uint32_t* a, uint32_t b0, uint32_t b1) {
    asm volatile(
        "mma.sync.aligned.m16n8k16.row.col.f32.bf16.bf16.f32 "
        "{%0,%1,%2,%3}, {%4,%5,%6,%7}, {%8,%9}, {%0,%1,%2,%3};"
        : "+f"(c[0]), "+f"(c[1]), "+f"(c[2]), "+f"(c[3])
        : "r"(a[0]), "r"(a[1]), "r"(a[2]), "r"(a[3]), "r"(b0), "r"(b1));
}

__device__ __forceinline__ void cp16(uint32_t dst, const void* src, uint32_t sz) {
    asm volatile("cp.async.cg.shared.global [%0], [%1], 16, %2;"
                 :: "r"(dst), "l"(src), "r"(sz));
}

__global__ __launch_bounds__(256) void sgemm_mma_kernel(const uint16_t* __restrict__ Ah,
                                                        const uint16_t* __restrict__ Al,
                                                        const uint16_t* __restrict__ Bh,
                                                        const uint16_t* __restrict__ Bl,
                                                        int M, int K, int KP) {
    extern __shared__ uint16_t sm[];
    // layout: [stage0 AH][stage0 AL][stage1 AH][stage1 AL][BsH][BsL]
    uint16_t* BsH = sm + 4 * SSTAGE;
    uint16_t* BsL = BsH + 128 * KP;
    uint32_t sbase;
    asm("{ .reg .u64 t; cvta.to.shared.u64 t, %1; cvt.u32.u64 %0, t; }"
        : "=r"(sbase) : "l"(sm));

    int tid = threadIdx.x, lane = tid & 31, wid = tid >> 5;
    int bm0 = blockIdx.y * 128, n0 = blockIdx.x * 128;
    int wm = wid >> 1, wn = wid & 1;
    int lq = lane >> 2, lr = lane & 3;

    // stage B (entire K) once — plain loads, L2-resident
    int kq = K >> 2;
    for (int idx = tid; idx < 128 * kq; idx += 256) {
        int n = idx / kq, c = (idx % kq) * 4;
        uint2 h = *(const uint2*)&Bh[(n0 + n) * 128 + c];
        uint2 l = *(const uint2*)&Bl[(n0 + n) * 128 + c];
        *(uint2*)&BsH[n * KP + c] = h;
        *(uint2*)&BsL[n * KP + c] = l;
    }

    float acc[2][8][4];
#pragma unroll
    for (int i = 0; i < 2; i++)
#pragma unroll
        for (int j = 0; j < 8; j++)
#pragma unroll
            for (int q = 0; q < 4; q++) acc[i][j][q] = 0.f;

    int nch = K >> 5;

    auto issue = [&](int ch) {
        int stg = ch & 1;
        int k0 = ch * 32;
        uint32_t baseH = sbase + (uint32_t)(2 * stg * SSTAGE) * 2u;
        uint32_t baseL = baseH + (uint32_t)SSTAGE * 2u;
#pragma unroll
        for (int it = 0; it < 2; it++) {
            int idx = tid + it * 256;           // 0..511: 16B groups
            int r = idx >> 2, g = idx & 3;      // row, 8-elem group
            int gr = bm0 + r;
            uint32_t sz = (gr < M) ? 16u : 0u;
            uint32_t doff = (uint32_t)(r * ASTRIDE + g * 8) * 2u;
            const uint16_t* sh = Ah + (size_t)gr * K + k0 + g * 8;
            const uint16_t* sl = Al + (size_t)gr * K + k0 + g * 8;
            cp16(baseH + doff, sh, sz);
            cp16(baseL + doff, sl, sz);
        }
        asm volatile("cp.async.commit_group;");
    };

    issue(0);
    for (int ch = 0; ch < nch; ch++) {
        if (ch + 1 < nch) issue(ch + 1);
        if (ch + 1 < nch) asm volatile("cp.async.wait_group 1;");
        else              asm volatile("cp.async.wait_group 0;");
        __syncthreads();
        int stg = ch & 1;
        uint16_t* AsH = sm + 2 * stg * SSTAGE;
        uint16_t* AsL = AsH + SSTAGE;
        int k0 = ch * 32;
#pragma unroll
        for (int ks = 0; ks < 2; ks++) {
            int kk = ks * 16;
            uint32_t ah[2][4], al[2][4];
#pragma unroll
            for (int i = 0; i < 2; i++) {
                int r = wm * 32 + i * 16 + lq;
                int base = r * ASTRIDE + kk + lr * 2;
                ah[i][0] = *(const uint32_t*)&AsH[base];
                ah[i][1] = *(const uint32_t*)&AsH[base + 8 * ASTRIDE];
                ah[i][2] = *(const uint32_t*)&AsH[base + 8];
                ah[i][3] = *(const uint32_t*)&AsH[base + 8 * ASTRIDE + 8];
                al[i][0] = *(const uint32_t*)&AsL[base];
                al[i][1] = *(const uint32_t*)&AsL[base + 8 * ASTRIDE];
                al[i][2] = *(const uint32_t*)&AsL[base + 8];
                al[i][3] = *(const uint32_t*)&AsL[base + 8 * ASTRIDE + 8];
            }
#pragma unroll
            for (int j = 0; j < 8; j++) {
                int n = wn * 64 + j * 8 + lq;
                int bb = n * KP + k0 + kk + lr * 2;
                uint32_t bh0 = *(const uint32_t*)&BsH[bb];
                uint32_t bh1 = *(const uint32_t*)&BsH[bb + 8];
                uint32_t bl0 = *(const uint32_t*)&BsL[bb];
                uint32_t bl1 = *(const uint32_t*)&BsL[bb + 8];
#pragma unroll
                for (int i = 0; i < 2; i++) {
                    mma16816(acc[i][j], ah[i], bh0, bh1);
                    mma16816(acc[i][j], al[i], bh0, bh1);
                    mma16816(acc[i][j], ah[i], bl0, bl1);
                }
            }
        }
        __syncthreads();
    }

    // epilogue: write fragments to g_tmp (+ packed att for cols 192-195)
#pragma unroll
    for (int i = 0; i < 2; i++) {
        int r0 = bm0 + wm * 32 + i * 16 + lq;
        int r1 = r0 + 8;
#pragma unroll
        for (int j = 0; j < 8; j++) {
            int col = n0 + wn * 64 + j * 8 + lr * 2;
            if (r0 < M) *(float2*)&g_tmp[r0 * ST + col] = make_float2(acc[i][j][0], acc[i][j][1]);
            if (r1 < M) *(float2*)&g_tmp[r1 * ST + col] = make_float2(acc[i][j][2], acc[i][j][3]);
        }
        // cols 192-195 live in (n0=128, wn=1, j=0, lr<2): lr=0 -> att.xy, lr=1 -> att.zw
        if (n0 == 128 && wn == 1 && lr < 2) {
            if (r0 < M) ((float2*)&g_att[r0])[lr] = make_float2(acc[i][0][0], acc[i][0][1]);
            if (r1 < M) ((float2*)&g_att[r1])[lr] = make_float2(acc[i][0][2], acc[i][0][3]);
        }
    }
}

// ---------------- per-destination aggregation ----------------
// one warp per destination node; per-edge {w0,w1,src} packed in g_ew4 ->
// one uniform LDG.128 + one gather LDG.128 per edge. 4-edge unroll.

__global__ __launch_bounds__(256) void gat_edge_kernel(const float* __restrict__ bAtt,
                                                       const float* __restrict__ bLin,
                                                       float* __restrict__ out,
                                                       int write_split) {
    int w = (blockIdx.x * blockDim.x + threadIdx.x) >> 5;
    int lane = threadIdx.x & 31;
    if (w >= NN) return;
    int beg = g_off[w], end = g_off[w + 1];
    int deg = end - beg;

    float den0 = 0.f, den1 = 0.f;
    float4 acc = make_float4(0.f, 0.f, 0.f, 0.f);
    int h = lane >> 4;        // head owned by this lane's feature slice
    int col = lane * 4;       // feature elements [col, col+4) of the 128-wide hs row
    int j = beg;
    for (; j + 4 <= end; j += 4) {
        float4 e0 = __ldg(&g_ew4[j]);
        float4 e1 = __ldg(&g_ew4[j + 1]);
        float4 e2 = __ldg(&g_ew4[j + 2]);
        float4 e3 = __ldg(&g_ew4[j + 3]);
        const float4 v0 = *(const float4*)&g_tmp[__float_as_int(e0.z) * ST + col];
        const float4 v1 = *(const float4*)&g_tmp[__float_as_int(e1.z) * ST + col];
        const float4 v2 = *(const float4*)&g_tmp[__float_as_int(e2.z) * ST + col];
        const float4 v3 = *(const float4*)&g_tmp[__float_as_int(e3.z) * ST + col];
        den0 += (e0.x + e1.x) + (e2.x + e3.x);
        den1 += (e0.y + e1.y) + (e2.y + e3.y);
        float w0 = h ? e0.y : e0.x;
        float w1 = h ? e1.y : e1.x;
        float w2 = h ? e2.y : e2.x;
        float w3 = h ? e3.y : e3.x;
        acc.x = fmaf(w0, v0.x, acc.x); acc.y = fmaf(w0, v0.y, acc.y);
        acc.z = fmaf(w0, v0.z, acc.z); acc.w = fmaf(w0, v0.w, acc.w);
        acc.x = fmaf(w1, v1.x, acc.x); acc.y = fmaf(w1, v1.y, acc.y);
        acc.z = fmaf(w1, v1.z, acc.z); acc.w = fmaf(w1, v1.w, acc.w);
        acc.x = fmaf(w2, v2.x, acc.x); acc.y = fmaf(w2, v2.y, acc.y);
        acc.z = fmaf(w2, v2.z, acc.z); acc.w = fmaf(w2, v2.w, acc.w);
        acc.x = fmaf(w3, v3.x, acc.x); acc.y = fmaf(w3, v3.y, acc.y);
        acc.z = fmaf(w3, v3.z, acc.z); acc.w = fmaf(w3, v3.w, acc.w);
    }
    for (; j < end; j++) {
        float4 e0 = __ldg(&g_ew4[j]);
        const float4 v0 = *(const float4*)&g_tmp[__float_as_int(e0.z) * ST + col];
        den0 += e0.x;
        den1 += e0.y;
        float w0 = h ? e0.y : e0.x;
        acc.x = fmaf(w0, v0.x, acc.x); acc.y = fmaf(w0, v0.y, acc.y);
        acc.z = fmaf(w0, v0.z, acc.z); acc.w = fmaf(w0, v0.w, acc.w);
    }
    float inv0 = deg > 0 ? 1.f / den0 : 0.f;
    float inv1 = deg > 0 ? 1.f / den1 : 0.f;
    float invh = h ? inv1 : inv0;
    float sx = acc.x * invh, sy = acc.y * invh, sz = acc.z * invh, sw = acc.w * invh;
    // combine heads: lanes 0..15 hold head0 elems [col,col+4), partner lane+16 holds head1
    float px = __shfl_xor_sync(0xffffffffu, sx, 16);
    float py = __shfl_xor_sync(0xffffffffu, sy, 16);
    float pz = __shfl_xor_sync(0xffffffffu, sz, 16);
    float pw = __shfl_xor_sync(0xffffffffu, sw, 16);
    if (lane < 16) {
        float4 skip = *(const float4*)&g_tmp[w * ST + 128 + col];
        float4 r;
        r.x = fmaxf(0.f, 0.5f * (sx + px) + bAtt[col + 0] + bLin[col + 0] + skip.x);
        r.y = fmaxf(0.f, 0.5f * (sy + py) + bAtt[col + 1] + bLin[col + 1] + skip.y);
        r.z = fmaxf(0.f, 0.5f * (sz + pz) + bAtt[col + 2] + bLin[col + 2] + skip.z);
        r.w = fmaxf(0.f, 0.5f * (sw + pw) + bAtt[col + 3] + bLin[col + 3] + skip.w);
        *(float4*)&out[w * 64 + col] = r;
        if (write_split) {
            uint16_t hh[4], ll[4];
            bf16_split(r.x, hh[0], ll[0]);
            bf16_split(r.y, hh[1], ll[1]);
            bf16_split(r.z, hh[2], ll[2]);
            bf16_split(r.w, hh[3], ll[3]);
            uint2 hp, lp;
            hp.x = (uint32_t)hh[0] | ((uint32_t)hh[1] << 16);
            hp.y = (uint32_t)hh[2] | ((uint32_t)hh[3] << 16);
            lp.x = (uint32_t)ll[0] | ((uint32_t)ll[1] << 16);
            lp.y = (uint32_t)ll[2] | ((uint32_t)ll[3] << 16);
            *(uint2*)&g_xh[w * 64 + col] = hp;
            *(uint2*)&g_xl[w * 64 + col] = lp;
        }
    }
}

// ---------------- launch ----------------

extern "C" void kernel_launch(void* const* d_in, const int* in_sizes, int n_in,
                              void* d_out, int out_size) {
    const float* x = (const float*)d_in[0];
    const int* ei = (const int*)d_in[1];
    const int* src = ei;
    const int* dst = ei + EE;
    const float* Ws[3] = {(const float*)d_in[2], (const float*)d_in[9], (const float*)d_in[16]};
    const float* Wd[3] = {(const float*)d_in[3], (const float*)d_in[10], (const float*)d_in[17]};
    const float* as_[3] = {(const float*)d_in[4], (const float*)d_in[11], (const float*)d_in[18]};
    const float* ad_[3] = {(const float*)d_in[5], (const float*)d_in[12], (const float*)d_in[19]};
    const float* b_[3] = {(const float*)d_in[6], (const float*)d_in[13], (const float*)d_in[20]};
    const float* Wl[3] = {(const float*)d_in[7], (const float*)d_in[14], (const float*)d_in[21]};
    const float* bl[3] = {(const float*)d_in[8], (const float*)d_in[15], (const float*)d_in[22]};
    float* out = (float*)d_out;

    float *h1, *h2;
    cudaGetSymbolAddress((void**)&h1, g_h1);
    cudaGetSymbolAddress((void**)&h2, g_h2);
    uint16_t *xh, *xl, *wh, *wl;
    cudaGetSymbolAddress((void**)&xh, g_xh);
    cudaGetSymbolAddress((void**)&xl, g_xl);
    cudaGetSymbolAddress((void**)&wh, g_wThb);
    cudaGetSymbolAddress((void**)&wl, g_wTlb);

    // side streams + fork/join events (created once; capture-safe fork-join)
    static cudaStream_t s1 = [] {
        cudaStream_t s;
        cudaStreamCreateWithFlags(&s, cudaStreamNonBlocking);
        return s;
    }();
    static cudaStream_t s2 = [] {
        cudaStream_t s;
        cudaStreamCreateWithFlags(&s, cudaStreamNonBlocking);
        return s;
    }();
    static cudaEvent_t evFork = [] {
        cudaEvent_t e;
        cudaEventCreateWithFlags(&e, cudaEventDisableTiming);
        return e;
    }();
    static cudaEvent_t evJoin = [] {
        cudaEvent_t e;
        cudaEventCreateWithFlags(&e, cudaEventDisableTiming);
        return e;
    }();
    static cudaEvent_t evW = [] {
        cudaEvent_t e;
        cudaEventCreateWithFlags(&e, cudaEventDisableTiming);
        return e;
    }();

    // max dynamic smem (layer 1: KP = 136)
    int smem_max = (4 * SSTAGE + 2 * 128 * 136) * (int)sizeof(uint16_t);
    cudaFuncSetAttribute(sgemm_mma_kernel, cudaFuncAttributeMaxDynamicSharedMemorySize, smem_max);

    // fork
    cudaEventRecord(evFork, 0);
    cudaStreamWaitEvent(s1, evFork, 0);
    cudaStreamWaitEvent(s2, evFork, 0);

    // s1: CSR build (only needed by ew of layer 0)
    zero_cnt_kernel<<<(NN + 255) / 256, 256, 0, s1>>>();
    count_kernel<<<(EE + 255) / 256, 256, 0, s1>>>(dst);
    scan_kernel<<<1, 1024, 0, s1>>>();
    fill_kernel<<<(EE + 255) / 256, 256, 0, s1>>>(dst);
    cudaEventRecord(evJoin, s1);

    // s2: all three weight-concat kernels (depend only on input weights)
    {
        int din = 128;
        for (int l = 0; l < 3; l++) {
            wcat_kernel<<<(din * 256 + 255) / 256, 256, 0, s2>>>(
                Ws[l], Wd[l], Wl[l], as_[l], ad_[l], din,
                wh + (size_t)l * 256 * 128, wl + (size_t)l * 256 * 128);
            din = 64;
        }
        cudaEventRecord(evW, s2);
    }

    // main stream
    split_x_kernel<<<(NN * 32 + 255) / 256, 256>>>(x);
    cudaStreamWaitEvent(0, evW, 0);

    int din = 128;
    for (int l = 0; l < 3; l++) {
        float* out_ptr = (l == 0) ? h1 : (l == 1 ? h2 : out);
        int KP = din + 8;
        int smem = (4 * SSTAGE + 2 * 128 * KP) * (int)sizeof(uint16_t);
        dim3 g(2, (NN + 127) / 128);
        sgemm_mma_kernel<<<g, 256, smem>>>(xh, xl,
                                           wh + (size_t)l * 256 * 128,
                                           wl + (size_t)l * 256 * 128,
                                           NN, din, KP);
        if (l == 0) cudaStreamWaitEvent(0, evJoin, 0);   // join: ew needs g_pos
        ew_kernel<<<(EE + 255) / 256, 256>>>(src, dst);
        gat_edge_kernel<<<(NN * 32 + 255) / 256, 256>>>(b_[l], bl[l], out_ptr, l < 2 ? 1 : 0);
        din = 64;
    }
}

// round 15
// speedup vs baseline: 1.7548x; 1.0222x over previous
#include <cuda_runtime.h>
#include <cuda_bf16.h>
#include <cstdint>

#define NN 50000
#define EE 800000
#define ST 256          // padded column stride of fused GEMM output
// tmp row layout: [0:128) hs (2 heads x 64), [128:192) skip = x@Wl,
//                 [192:194) als, [194:196) ald, [196:256) zero pad

__device__ __align__(128) float g_tmp[NN * ST];
__device__ __align__(128) float g_h1[NN * 64];
__device__ __align__(128) float g_h2[NN * 64];
__device__ __align__(128) float4 g_att[NN];            // {als0, als1, ald0, ald1}
__device__ __align__(128) float4 g_ew4[EE];            // {w0, w1, bitcast(src), 0} CSR order
__device__ __align__(128) uint16_t g_xh[NN * 128];     // layer input, bf16 hi
__device__ __align__(128) uint16_t g_xl[NN * 128];     // layer input, bf16 lo (residual)
__device__ __align__(128) uint16_t g_wThb[3][256 * 128];  // per-layer fused weights, bf16 hi
__device__ __align__(128) uint16_t g_wTlb[3][256 * 128];  // per-layer fused weights, bf16 lo
__device__ int g_off[NN + 1];
__device__ int g_cur[NN];
__device__ int g_pos[EE];                              // original edge -> CSR slot

// ---------------- CSR build (by destination) ----------------

__global__ void zero_cnt_kernel() {
    int i = blockIdx.x * blockDim.x + threadIdx.x;
    if (i < NN) g_cur[i] = 0;
}

__global__ void count_kernel(const int* __restrict__ dst) {
    int e = blockIdx.x * blockDim.x + threadIdx.x;
    if (e < EE) atomicAdd(&g_cur[dst[e]], 1);
}

__global__ void scan_kernel() {
    __shared__ int part[1024];
    int tid = threadIdx.x;
    const int CH = (NN + 1023) / 1024;
    int base = tid * CH;
    int s = 0;
    for (int j = 0; j < CH; j++) {
        int i = base + j;
        if (i < NN) s += g_cur[i];
    }
    part[tid] = s;
    __syncthreads();
    if (tid == 0) {
        int r = 0;
        for (int i = 0; i < 1024; i++) { int t = part[i]; part[i] = r; r += t; }
        g_off[NN] = r;
    }
    __syncthreads();
    int r = part[tid];
    for (int j = 0; j < CH; j++) {
        int i = base + j;
        if (i < NN) {
            int d = g_cur[i];
            g_off[i] = r;
            g_cur[i] = r;   // cursor for fill pass
            r += d;
        }
    }
}

__global__ void fill_kernel(const int* __restrict__ dst) {
    int e = blockIdx.x * blockDim.x + threadIdx.x;
    if (e < EE) g_pos[e] = atomicAdd(&g_cur[dst[e]], 1);
}

// ---------------- bf16 split helpers ----------------

__device__ __forceinline__ void bf16_split(float v, uint16_t& hi, uint16_t& lo) {
    __nv_bfloat16 h = __float2bfloat16(v);
    float r = v - __bfloat162float(h);
    __nv_bfloat16 l = __float2bfloat16(r);
    hi = *reinterpret_cast<uint16_t*>(&h);
    lo = *reinterpret_cast<uint16_t*>(&l);
}

// split layer-1 input x [NN,128] into bf16 hi/lo
__global__ void split_x_kernel(const float* __restrict__ x) {
    int t = blockIdx.x * blockDim.x + threadIdx.x;
    if (t >= NN * 32) return;
    float4 v = *(const float4*)&x[t * 4];
    uint16_t h[4], l[4];
    bf16_split(v.x, h[0], l[0]);
    bf16_split(v.y, h[1], l[1]);
    bf16_split(v.z, h[2], l[2]);
    bf16_split(v.w, h[3], l[3]);
    uint2 hp, lp;
    hp.x = (uint32_t)h[0] | ((uint32_t)h[1] << 16);
    hp.y = (uint32_t)h[2] | ((uint32_t)h[3] << 16);
    lp.x = (uint32_t)l[0] | ((uint32_t)l[1] << 16);
    lp.y = (uint32_t)l[2] | ((uint32_t)l[3] << 16);
    *(uint2*)&g_xh[t * 4] = hp;
    *(uint2*)&g_xl[t * 4] = lp;
}

// per-edge softmax weights + packed src (edge-parallel, written to CSR slots).
// no max-subtraction: logits are O(1)-bounded, exp cannot overflow fp32.
__global__ void ew_kernel(const int* __restrict__ src, const int* __restrict__ dst) {
    int e = blockIdx.x * blockDim.x + threadIdx.x;
    if (e >= EE) return;
    int s = src[e];
    float4 as_ = g_att[s];
    float4 ad_ = g_att[dst[e]];
    float l0 = as_.x + ad_.z;
    float l1 = as_.y + ad_.w;
    l0 = l0 > 0.f ? l0 : 0.2f * l0;
    l1 = l1 > 0.f ? l1 : 0.2f * l1;
    g_ew4[g_pos[e]] = make_float4(__expf(l0), __expf(l1), __int_as_float(s), 0.f);
}

// ---------------- fused weight concat -> transposed bf16 hi/lo ----------------

__global__ void wcat_kernel(const float* __restrict__ Ws, const float* __restrict__ Wd,
                            const float* __restrict__ Wl, const float* __restrict__ as_,
                            const float* __restrict__ ad_, int din,
                            uint16_t* __restrict__ outH, uint16_t* __restrict__ outL) {
    int t = blockIdx.x * blockDim.x + threadIdx.x;
    if (t >= din * 256) return;
    int k = t >> 8, col = t & 255;
    float v = 0.f;
    if (col < 128) {
        v = Ws[k * 128 + col];
    } else if (col < 192) {
        v = Wl[k * 64 + (col - 128)];
    } else if (col < 194) {
        int h = col - 192;
        float s = 0.f;
        for (int c = 0; c < 64; c++) s += Ws[k * 128 + h * 64 + c] * as_[h * 64 + c];
        v = s;
    } else if (col < 196) {
        int h = col - 194;
        float s = 0.f;
        for (int c = 0; c < 64; c++) s += Wd[k * 128 + h * 64 + c] * ad_[h * 64 + c];
        v = s;
    }
    uint16_t hi, lo;
    bf16_split(v, hi, lo);
    outH[col * 128 + k] = hi;
    outL[col * 128 + k] = lo;
}

// ---------------- tensor-core GEMM via mma.sync bf16 (3-product split) ----------------
// C[M, n0:n0+128] = A[M,K] @ Wcat[K, n0:n0+128].  CTA 128 rows; 8 warps (4M x 2N),
// warp tile 32x64. A pre-split bf16 hi/lo; cp.async, 2-stage pipeline.
// Launched per column half: n0=128 (att+skip) first, then n0=0 (hs).
// Epilogue also writes packed g_att (cols 192-195, n0=128 half).

#define ASTRIDE 40
#define SSTAGE (128 * ASTRIDE)   // elems per (hi or lo) stage buffer

__device__ __forceinline__ void mma16816(float* c, const uint32_t* a, uint32_t b0, uint32_t b1) {
    asm volatile(
        "mma.sync.aligned.m16n8k16.row.col.f32.bf16.bf16.f32 "
        "{%0,%1,%2,%3}, {%4,%5,%6,%7}, {%8,%9}, {%0,%1,%2,%3};"
        : "+f"(c[0]), "+f"(c[1]), "+f"(c[2]), "+f"(c[3])
        : "r"(a[0]), "r"(a[1]), "r"(a[2]), "r"(a[3]), "r"(b0), "r"(b1));
}

__device__ __forceinline__ void cp16(uint32_t dst, const void* src, uint32_t sz) {
    asm volatile("cp.async.cg.shared.global [%0], [%1], 16, %2;"
                 :: "r"(dst), "l"(src), "r"(sz));
}

__global__ __launch_bounds__(256) void sgemm_mma_kernel(const uint16_t* __restrict__ Ah,
                                                        const uint16_t* __restrict__ Al,
                                                        const uint16_t* __restrict__ Bh,
                                                        const uint16_t* __restrict__ Bl,
                                                        int M, int K, int KP, int n0) {
    extern __shared__ uint16_t sm[];
    // layout: [stage0 AH][stage0 AL][stage1 AH][stage1 AL][BsH][BsL]
    uint16_t* BsH = sm + 4 * SSTAGE;
    uint16_t* BsL = BsH + 128 * KP;
    uint32_t sbase;
    asm("{ .reg .u64 t; cvta.to.shared.u64 t, %1; cvt.u32.u64 %0, t; }"
        : "=r"(sbase) : "l"(sm));

    int tid = threadIdx.x, lane = tid & 31, wid = tid >> 5;
    int bm0 = blockIdx.y * 128;
    int wm = wid >> 1, wn = wid & 1;
    int lq = lane >> 2, lr = lane & 3;

    // stage B (entire K) once — plain loads, L2-resident
    int kq = K >> 2;
    for (int idx = tid; idx < 128 * kq; idx += 256) {
        int n = idx / kq, c = (idx % kq) * 4;
        uint2 h = *(const uint2*)&Bh[(n0 + n) * 128 + c];
        uint2 l = *(const uint2*)&Bl[(n0 + n) * 128 + c];
        *(uint2*)&BsH[n * KP + c] = h;
        *(uint2*)&BsL[n * KP + c] = l;
    }

    float acc[2][8][4];
#pragma unroll
    for (int i = 0; i < 2; i++)
#pragma unroll
        for (int j = 0; j < 8; j++)
#pragma unroll
            for (int q = 0; q < 4; q++) acc[i][j][q] = 0.f;

    int nch = K >> 5;

    auto issue = [&](int ch) {
        int stg = ch & 1;
        int k0 = ch * 32;
        uint32_t baseH = sbase + (uint32_t)(2 * stg * SSTAGE) * 2u;
        uint32_t baseL = baseH + (uint32_t)SSTAGE * 2u;
#pragma unroll
        for (int it = 0; it < 2; it++) {
            int idx = tid + it * 256;           // 0..511: 16B groups
            int r = idx >> 2, g = idx & 3;      // row, 8-elem group
            int gr = bm0 + r;
            uint32_t sz = (gr < M) ? 16u : 0u;
            uint32_t doff = (uint32_t)(r * ASTRIDE + g * 8) * 2u;
            const uint16_t* sh = Ah + (size_t)gr * K + k0 + g * 8;
            const uint16_t* sl = Al + (size_t)gr * K + k0 + g * 8;
            cp16(baseH + doff, sh, sz);
            cp16(baseL + doff, sl, sz);
        }
        asm volatile("cp.async.commit_group;");
    };

    issue(0);
    for (int ch = 0; ch < nch; ch++) {
        if (ch + 1 < nch) issue(ch + 1);
        if (ch + 1 < nch) asm volatile("cp.async.wait_group 1;");
        else              asm volatile("cp.async.wait_group 0;");
        __syncthreads();
        int stg = ch & 1;
        uint16_t* AsH = sm + 2 * stg * SSTAGE;
        uint16_t* AsL = AsH + SSTAGE;
        int k0 = ch * 32;
#pragma unroll
        for (int ks = 0; ks < 2; ks++) {
            int kk = ks * 16;
            uint32_t ah[2][4], al[2][4];
#pragma unroll
            for (int i = 0; i < 2; i++) {
                int r = wm * 32 + i * 16 + lq;
                int base = r * ASTRIDE + kk + lr * 2;
                ah[i][0] = *(const uint32_t*)&AsH[base];
                ah[i][1] = *(const uint32_t*)&AsH[base + 8 * ASTRIDE];
                ah[i][2] = *(const uint32_t*)&AsH[base + 8];
                ah[i][3] = *(const uint32_t*)&AsH[base + 8 * ASTRIDE + 8];
                al[i][0] = *(const uint32_t*)&AsL[base];
                al[i][1] = *(const uint32_t*)&AsL[base + 8 * ASTRIDE];
                al[i][2] = *(const uint32_t*)&AsL[base + 8];
                al[i][3] = *(const uint32_t*)&AsL[base + 8 * ASTRIDE + 8];
            }
#pragma unroll
            for (int j = 0; j < 8; j++) {
                int n = wn * 64 + j * 8 + lq;
                int bb = n * KP + k0 + kk + lr * 2;
                uint32_t bh0 = *(const uint32_t*)&BsH[bb];
                uint32_t bh1 = *(const uint32_t*)&BsH[bb + 8];
                uint32_t bl0 = *(const uint32_t*)&BsL[bb];
                uint32_t bl1 = *(const uint32_t*)&BsL[bb + 8];
#pragma unroll
                for (int i = 0; i < 2; i++) {
                    mma16816(acc[i][j], ah[i], bh0, bh1);
                    mma16816(acc[i][j], al[i], bh0, bh1);
                    mma16816(acc[i][j], ah[i], bl0, bl1);
                }
            }
        }
        __syncthreads();
    }

    // epilogue: write fragments to g_tmp (+ packed att for cols 192-195)
#pragma unroll
    for (int i = 0; i < 2; i++) {
        int r0 = bm0 + wm * 32 + i * 16 + lq;
        int r1 = r0 + 8;
#pragma unroll
        for (int j = 0; j < 8; j++) {
            int col = n0 + wn * 64 + j * 8 + lr * 2;
            if (r0 < M) *(float2*)&g_tmp[r0 * ST + col] = make_float2(acc[i][j][0], acc[i][j][1]);
            if (r1 < M) *(float2*)&g_tmp[r1 * ST + col] = make_float2(acc[i][j][2], acc[i][j][3]);
        }
        // cols 192-195 live in (n0=128, wn=1, j=0, lr<2): lr=0 -> att.xy, lr=1 -> att.zw
        if (n0 == 128 && wn == 1 && lr < 2) {
            if (r0 < M) ((float2*)&g_att[r0])[lr] = make_float2(acc[i][0][0], acc[i][0][1]);
            if (r1 < M) ((float2*)&g_att[r1])[lr] = make_float2(acc[i][0][2], acc[i][0][3]);
        }
    }
}

// ---------------- per-destination aggregation ----------------
// one warp per destination node; per-edge {w0,w1,src} packed in g_ew4 ->
// one uniform LDG.128 + one gather LDG.128 per edge. 4-edge unroll.

__global__ __launch_bounds__(256) void gat_edge_kernel(const float* __restrict__ bAtt,
                                                       const float* __restrict__ bLin,
                                                       float* __restrict__ out,
                                                       int write_split) {
    int w = (blockIdx.x * blockDim.x + threadIdx.x) >> 5;
    int lane = threadIdx.x & 31;
    if (w >= NN) return;
    int beg = g_off[w], end = g_off[w + 1];
    int deg = end - beg;

    float den0 = 0.f, den1 = 0.f;
    float4 acc = make_float4(0.f, 0.f, 0.f, 0.f);
    int h = lane >> 4;        // head owned by this lane's feature slice
    int col = lane * 4;       // feature elements [col, col+4) of the 128-wide hs row
    int j = beg;
    for (; j + 4 <= end; j += 4) {
        float4 e0 = __ldg(&g_ew4[j]);
        float4 e1 = __ldg(&g_ew4[j + 1]);
        float4 e2 = __ldg(&g_ew4[j + 2]);
        float4 e3 = __ldg(&g_ew4[j + 3]);
        const float4 v0 = *(const float4*)&g_tmp[__float_as_int(e0.z) * ST + col];
        const float4 v1 = *(const float4*)&g_tmp[__float_as_int(e1.z) * ST + col];
        const float4 v2 = *(const float4*)&g_tmp[__float_as_int(e2.z) * ST + col];
        const float4 v3 = *(const float4*)&g_tmp[__float_as_int(e3.z) * ST + col];
        den0 += (e0.x + e1.x) + (e2.x + e3.x);
        den1 += (e0.y + e1.y) + (e2.y + e3.y);
        float w0 = h ? e0.y : e0.x;
        float w1 = h ? e1.y : e1.x;
        float w2 = h ? e2.y : e2.x;
        float w3 = h ? e3.y : e3.x;
        acc.x = fmaf(w0, v0.x, acc.x); acc.y = fmaf(w0, v0.y, acc.y);
        acc.z = fmaf(w0, v0.z, acc.z); acc.w = fmaf(w0, v0.w, acc.w);
        acc.x = fmaf(w1, v1.x, acc.x); acc.y = fmaf(w1, v1.y, acc.y);
        acc.z = fmaf(w1, v1.z, acc.z); acc.w = fmaf(w1, v1.w, acc.w);
        acc.x = fmaf(w2, v2.x, acc.x); acc.y = fmaf(w2, v2.y, acc.y);
        acc.z = fmaf(w2, v2.z, acc.z); acc.w = fmaf(w2, v2.w, acc.w);
        acc.x = fmaf(w3, v3.x, acc.x); acc.y = fmaf(w3, v3.y, acc.y);
        acc.z = fmaf(w3, v3.z, acc.z); acc.w = fmaf(w3, v3.w, acc.w);
    }
    for (; j < end; j++) {
        float4 e0 = __ldg(&g_ew4[j]);
        const float4 v0 = *(const float4*)&g_tmp[__float_as_int(e0.z) * ST + col];
        den0 += e0.x;
        den1 += e0.y;
        float w0 = h ? e0.y : e0.x;
        acc.x = fmaf(w0, v0.x, acc.x); acc.y = fmaf(w0, v0.y, acc.y);
        acc.z = fmaf(w0, v0.z, acc.z); acc.w = fmaf(w0, v0.w, acc.w);
    }
    float inv0 = deg > 0 ? 1.f / den0 : 0.f;
    float inv1 = deg > 0 ? 1.f / den1 : 0.f;
    float invh = h ? inv1 : inv0;
    float sx = acc.x * invh, sy = acc.y * invh, sz = acc.z * invh, sw = acc.w * invh;
    // combine heads: lanes 0..15 hold head0 elems [col,col+4), partner lane+16 holds head1
    float px = __shfl_xor_sync(0xffffffffu, sx, 16);
    float py = __shfl_xor_sync(0xffffffffu, sy, 16);
    float pz = __shfl_xor_sync(0xffffffffu, sz, 16);
    float pw = __shfl_xor_sync(0xffffffffu, sw, 16);
    if (lane < 16) {
        float4 skip = *(const float4*)&g_tmp[w * ST + 128 + col];
        float4 r;
        r.x = fmaxf(0.f, 0.5f * (sx + px) + bAtt[col + 0] + bLin[col + 0] + skip.x);
        r.y = fmaxf(0.f, 0.5f * (sy + py) + bAtt[col + 1] + bLin[col + 1] + skip.y);
        r.z = fmaxf(0.f, 0.5f * (sz + pz) + bAtt[col + 2] + bLin[col + 2] + skip.z);
        r.w = fmaxf(0.f, 0.5f * (sw + pw) + bAtt[col + 3] + bLin[col + 3] + skip.w);
        *(float4*)&out[w * 64 + col] = r;
        if (write_split) {
            uint16_t hh[4], ll[4];
            bf16_split(r.x, hh[0], ll[0]);
            bf16_split(r.y, hh[1], ll[1]);
            bf16_split(r.z, hh[2], ll[2]);
            bf16_split(r.w, hh[3], ll[3]);
            uint2 hp, lp;
            hp.x = (uint32_t)hh[0] | ((uint32_t)hh[1] << 16);
            hp.y = (uint32_t)hh[2] | ((uint32_t)hh[3] << 16);
            lp.x = (uint32_t)ll[0] | ((uint32_t)ll[1] << 16);
            lp.y = (uint32_t)ll[2] | ((uint32_t)ll[3] << 16);
            *(uint2*)&g_xh[w * 64 + col] = hp;
            *(uint2*)&g_xl[w * 64 + col] = lp;
        }
    }
}

// ---------------- launch ----------------

extern "C" void kernel_launch(void* const* d_in, const int* in_sizes, int n_in,
                              void* d_out, int out_size) {
    const float* x = (const float*)d_in[0];
    const int* ei = (const int*)d_in[1];
    const int* src = ei;
    const int* dst = ei + EE;
    const float* Ws[3] = {(const float*)d_in[2], (const float*)d_in[9], (const float*)d_in[16]};
    const float* Wd[3] = {(const float*)d_in[3], (const float*)d_in[10], (const float*)d_in[17]};
    const float* as_[3] = {(const float*)d_in[4], (const float*)d_in[11], (const float*)d_in[18]};
    const float* ad_[3] = {(const float*)d_in[5], (const float*)d_in[12], (const float*)d_in[19]};
    const float* b_[3] = {(const float*)d_in[6], (const float*)d_in[13], (const float*)d_in[20]};
    const float* Wl[3] = {(const float*)d_in[7], (const float*)d_in[14], (const float*)d_in[21]};
    const float* bl[3] = {(const float*)d_in[8], (const float*)d_in[15], (const float*)d_in[22]};
    float* out = (float*)d_out;

    float *h1, *h2;
    cudaGetSymbolAddress((void**)&h1, g_h1);
    cudaGetSymbolAddress((void**)&h2, g_h2);
    uint16_t *xh, *xl, *wh, *wl;
    cudaGetSymbolAddress((void**)&xh, g_xh);
    cudaGetSymbolAddress((void**)&xl, g_xl);
    cudaGetSymbolAddress((void**)&wh, g_wThb);
    cudaGetSymbolAddress((void**)&wl, g_wTlb);

    // side streams + events (created once; capture-safe fork-join)
    static cudaStream_t s1 = [] {
        cudaStream_t s;
        cudaStreamCreateWithFlags(&s, cudaStreamNonBlocking);
        return s;
    }();
    static cudaStream_t s2 = [] {
        cudaStream_t s;
        cudaStreamCreateWithFlags(&s, cudaStreamNonBlocking);
        return s;
    }();
    static cudaStream_t s3 = [] {
        cudaStream_t s;
        cudaStreamCreateWithFlags(&s, cudaStreamNonBlocking);
        return s;
    }();
    static cudaEvent_t evFork = [] {
        cudaEvent_t e;
        cudaEventCreateWithFlags(&e, cudaEventDisableTiming);
        return e;
    }();
    static cudaEvent_t evJoin = [] {
        cudaEvent_t e;
        cudaEventCreateWithFlags(&e, cudaEventDisableTiming);
        return e;
    }();
    static cudaEvent_t evW = [] {
        cudaEvent_t e;
        cudaEventCreateWithFlags(&e, cudaEventDisableTiming);
        return e;
    }();
    static cudaEvent_t evAtt = [] {
        cudaEvent_t e;
        cudaEventCreateWithFlags(&e, cudaEventDisableTiming);
        return e;
    }();
    static cudaEvent_t evEw = [] {
        cudaEvent_t e;
        cudaEventCreateWithFlags(&e, cudaEventDisableTiming);
        return e;
    }();

    // max dynamic smem (layer 1: KP = 136)
    int smem_max = (4 * SSTAGE + 2 * 128 * 136) * (int)sizeof(uint16_t);
    cudaFuncSetAttribute(sgemm_mma_kernel, cudaFuncAttributeMaxDynamicSharedMemorySize, smem_max);

    // fork
    cudaEventRecord(evFork, 0);
    cudaStreamWaitEvent(s1, evFork, 0);
    cudaStreamWaitEvent(s2, evFork, 0);

    // s1: CSR build (only needed by ew of layer 0)
    zero_cnt_kernel<<<(NN + 255) / 256, 256, 0, s1>>>();
    count_kernel<<<(EE + 255) / 256, 256, 0, s1>>>(dst);
    scan_kernel<<<1, 1024, 0, s1>>>();
    fill_kernel<<<(EE + 255) / 256, 256, 0, s1>>>(dst);
    cudaEventRecord(evJoin, s1);

    // s2: all three weight-concat kernels (depend only on input weights)
    {
        int din = 128;
        for (int l = 0; l < 3; l++) {
            wcat_kernel<<<(din * 256 + 255) / 256, 256, 0, s2>>>(
                Ws[l], Wd[l], Wl[l], as_[l], ad_[l], din,
                wh + (size_t)l * 256 * 128, wl + (size_t)l * 256 * 128);
            din = 64;
        }
        cudaEventRecord(evW, s2);
    }

    // main stream
    split_x_kernel<<<(NN * 32 + 255) / 256, 256>>>(x);
    cudaStreamWaitEvent(0, evW, 0);

    int din = 128;
    for (int l = 0; l < 3; l++) {
        float* out_ptr = (l == 0) ? h1 : (l == 1 ? h2 : out);
        int KP = din + 8;
        int smem = (4 * SSTAGE + 2 * 128 * KP) * (int)sizeof(uint16_t);
        const uint16_t* Bh = wh + (size_t)l * 256 * 128;
        const uint16_t* Bl = wl + (size_t)l * 256 * 128;
        dim3 gh(1, (NN + 127) / 128);

        // att+skip half first (produces g_att)
        sgemm_mma_kernel<<<gh, 256, smem>>>(xh, xl, Bh, Bl, NN, din, KP, 128);
        cudaEventRecord(evAtt, 0);

        // ew on side stream, overlapped with the hs half
        cudaStreamWaitEvent(s3, evAtt, 0);
        if (l == 0) cudaStreamWaitEvent(s3, evJoin, 0);   // ew needs g_pos
        ew_kernel<<<(EE + 255) / 256, 256, 0, s3>>>(src, dst);
        cudaEventRecord(evEw, s3);

        // hs half on main stream
        sgemm_mma_kernel<<<gh, 256, smem>>>(xh, xl, Bh, Bl, NN, din, KP, 0);

        cudaStreamWaitEvent(0, evEw, 0);
        gat_edge_kernel<<<(NN * 32 + 255) / 256, 256>>>(b_[l], bl[l], out_ptr, l < 2 ? 1 : 0);
        din = 64;
    }
}

// round 16
// speedup vs baseline: 1.7641x; 1.0053x over previous
#include <cuda_runtime.h>
#include <cuda_bf16.h>
#include <cstdint>

#define NN 50000
#define EE 800000
#define ST 256          // padded column stride of fused GEMM output
// tmp row layout: [0:128) hs (2 heads x 64), [128:192) skip = x@Wl,
//                 [192:194) als, [194:196) ald, [196:256) zero pad

__device__ __align__(128) float g_tmp[NN * ST];
__device__ __align__(128) float g_h1[NN * 64];
__device__ __align__(128) float g_h2[NN * 64];
__device__ __align__(128) float4 g_att[NN];            // {als0, als1, ald0, ald1}
__device__ __align__(128) float4 g_ew4[EE];            // {w0, w1, bitcast(src), 0} CSR order
__device__ __align__(128) uint16_t g_xh[NN * 128];     // layer input, bf16 hi
__device__ __align__(128) uint16_t g_xl[NN * 128];     // layer input, bf16 lo (residual)
__device__ __align__(128) uint16_t g_wThb[3][256 * 128];  // per-layer fused weights, bf16 hi
__device__ __align__(128) uint16_t g_wTlb[3][256 * 128];  // per-layer fused weights, bf16 lo
__device__ int g_off[NN + 1];
__device__ int g_cur[NN];
__device__ int g_pos[EE];                              // original edge -> CSR slot

// ---------------- CSR build (by destination) ----------------

__global__ void zero_cnt_kernel() {
    int i = blockIdx.x * blockDim.x + threadIdx.x;
    if (i < NN) g_cur[i] = 0;
}

__global__ void count_kernel(const int* __restrict__ dst) {
    int e = blockIdx.x * blockDim.x + threadIdx.x;
    if (e < EE) atomicAdd(&g_cur[dst[e]], 1);
}

__global__ void scan_kernel() {
    __shared__ int part[1024];
    int tid = threadIdx.x;
    const int CH = (NN + 1023) / 1024;
    int base = tid * CH;
    int s = 0;
    for (int j = 0; j < CH; j++) {
        int i = base + j;
        if (i < NN) s += g_cur[i];
    }
    part[tid] = s;
    __syncthreads();
    if (tid == 0) {
        int r = 0;
        for (int i = 0; i < 1024; i++) { int t = part[i]; part[i] = r; r += t; }
        g_off[NN] = r;
    }
    __syncthreads();
    int r = part[tid];
    for (int j = 0; j < CH; j++) {
        int i = base + j;
        if (i < NN) {
            int d = g_cur[i];
            g_off[i] = r;
            g_cur[i] = r;   // cursor for fill pass
            r += d;
        }
    }
}

__global__ void fill_kernel(const int* __restrict__ dst) {
    int e = blockIdx.x * blockDim.x + threadIdx.x;
    if (e < EE) g_pos[e] = atomicAdd(&g_cur[dst[e]], 1);
}

// ---------------- bf16 split helpers ----------------

__device__ __forceinline__ void bf16_split(float v, uint16_t& hi, uint16_t& lo) {
    __nv_bfloat16 h = __float2bfloat16(v);
    float r = v - __bfloat162float(h);
    __nv_bfloat16 l = __float2bfloat16(r);
    hi = *reinterpret_cast<uint16_t*>(&h);
    lo = *reinterpret_cast<uint16_t*>(&l);
}

// split layer-1 input x [NN,128] into bf16 hi/lo
__global__ void split_x_kernel(const float* __restrict__ x) {
    int t = blockIdx.x * blockDim.x + threadIdx.x;
    if (t >= NN * 32) return;
    float4 v = *(const float4*)&x[t * 4];
    uint16_t h[4], l[4];
    bf16_split(v.x, h[0], l[0]);
    bf16_split(v.y, h[1], l[1]);
    bf16_split(v.z, h[2], l[2]);
    bf16_split(v.w, h[3], l[3]);
    uint2 hp, lp;
    hp.x = (uint32_t)h[0] | ((uint32_t)h[1] << 16);
    hp.y = (uint32_t)h[2] | ((uint32_t)h[3] << 16);
    lp.x = (uint32_t)l[0] | ((uint32_t)l[1] << 16);
    lp.y = (uint32_t)l[2] | ((uint32_t)l[3] << 16);
    *(uint2*)&g_xh[t * 4] = hp;
    *(uint2*)&g_xl[t * 4] = lp;
}

// per-edge softmax weights + packed src (edge-parallel, written to CSR slots).
// no max-subtraction: logits are O(1)-bounded, exp cannot overflow fp32.
__global__ void ew_kernel(const int* __restrict__ src, const int* __restrict__ dst) {
    int e = blockIdx.x * blockDim.x + threadIdx.x;
    if (e >= EE) return;
    int s = src[e];
    float4 as_ = g_att[s];
    float4 ad_ = g_att[dst[e]];
    float l0 = as_.x + ad_.z;
    float l1 = as_.y + ad_.w;
    l0 = l0 > 0.f ? l0 : 0.2f * l0;
    l1 = l1 > 0.f ? l1 : 0.2f * l1;
    g_ew4[g_pos[e]] = make_float4(__expf(l0), __expf(l1), __int_as_float(s), 0.f);
}

// ---------------- fused weight concat -> transposed bf16 hi/lo ----------------

__global__ void wcat_kernel(const float* __restrict__ Ws, const float* __restrict__ Wd,
                            const float* __restrict__ Wl, const float* __restrict__ as_,
                            const float* __restrict__ ad_, int din,
                            uint16_t* __restrict__ outH, uint16_t* __restrict__ outL) {
    int t = blockIdx.x * blockDim.x + threadIdx.x;
    if (t >= din * 256) return;
    int k = t >> 8, col = t & 255;
    float v = 0.f;
    if (col < 128) {
        v = Ws[k * 128 + col];
    } else if (col < 192) {
        v = Wl[k * 64 + (col - 128)];
    } else if (col < 194) {
        int h = col - 192;
        float s = 0.f;
        for (int c = 0; c < 64; c++) s += Ws[k * 128 + h * 64 + c] * as_[h * 64 + c];
        v = s;
    } else if (col < 196) {
        int h = col - 194;
        float s = 0.f;
        for (int c = 0; c < 64; c++) s += Wd[k * 128 + h * 64 + c] * ad_[h * 64 + c];
        v = s;
    }
    uint16_t hi, lo;
    bf16_split(v, hi, lo);
    outH[col * 128 + k] = hi;
    outL[col * 128 + k] = lo;
}

// ---------------- tensor-core GEMM via mma.sync bf16 (3-product split) ----------------
// C[M, n0:n0+128] = A[M,K] @ Wcat[K, n0:n0+128].  CTA 128 rows; 8 warps (4M x 2N),
// warp tile 32x64. A pre-split bf16 hi/lo; cp.async, 2-stage pipeline.
// Launched per column half: n0=128 (att+skip) first, then n0=0 (hs).
// Epilogue also writes packed g_att (cols 192-195, n0=128 half).
// __launch_bounds__(256, 2): force regs <= 128 so 2 CTAs co-reside per SM
// (smem fits 2x at all layer sizes; inter-CTA overlap hides staging latency).

#define ASTRIDE 40
#define SSTAGE (128 * ASTRIDE)   // elems per (hi or lo) stage buffer

__device__ __forceinline__ void mma16816(float* c, const uint32_t* a, uint32_t b0, uint32_t b1) {
    asm volatile(
        "mma.sync.aligned.m16n8k16.row.col.f32.bf16.bf16.f32 "
        "{%0,%1,%2,%3}, {%4,%5,%6,%7}, {%8,%9}, {%0,%1,%2,%3};"
        : "+f"(c[0]), "+f"(c[1]), "+f"(c[2]), "+f"(c[3])
        : "r"(a[0]), "r"(a[1]), "r"(a[2]), "r"(a[3]), "r"(b0), "r"(b1));
}

__device__ __forceinline__ void cp16(uint32_t dst, const void* src, uint32_t sz) {
    asm volatile("cp.async.cg.shared.global [%0], [%1], 16, %2;"
                 :: "r"(dst), "l"(src), "r"(sz));
}

__global__ __launch_bounds__(256, 2) void sgemm_mma_kernel(const uint16_t* __restrict__ Ah,
                                                           const uint16_t* __restrict__ Al,
                                                           const uint16_t* __restrict__ Bh,
                                                           const uint16_t* __restrict__ Bl,
                                                           int M, int K, int KP, int n0) {
    extern __shared__ uint16_t sm[];
    // layout: [stage0 AH][stage0 AL][stage1 AH][stage1 AL][BsH][BsL]
    uint16_t* BsH = sm + 4 * SSTAGE;
    uint16_t* BsL = BsH + 128 * KP;
    uint32_t sbase;
    asm("{ .reg .u64 t; cvta.to.shared.u64 t, %1; cvt.u32.u64 %0, t; }"
        : "=r"(sbase) : "l"(sm));

    int tid = threadIdx.x, lane = tid & 31, wid = tid >> 5;
    int bm0 = blockIdx.y * 128;
    int wm = wid >> 1, wn = wid & 1;
    int lq = lane >> 2, lr = lane & 3;

    // stage B (entire K) once — plain loads, L2-resident
    int kq = K >> 2;
    for (int idx = tid; idx < 128 * kq; idx += 256) {
        int n = idx / kq, c = (idx % kq) * 4;
        uint2 h = *(const uint2*)&Bh[(n0 + n) * 128 + c];
        uint2 l = *(const uint2*)&Bl[(n0 + n) * 128 + c];
        *(uint2*)&BsH[n * KP + c] = h;
        *(uint2*)&BsL[n * KP + c] = l;
    }

    float acc[2][8][4];
#pragma unroll
    for (int i = 0; i < 2; i++)
#pragma unroll
        for (int j = 0; j < 8; j++)
#pragma unroll
            for (int q = 0; q < 4; q++) acc[i][j][q] = 0.f;

    int nch = K >> 5;

    auto issue = [&](int ch) {
        int stg = ch & 1;
        int k0 = ch * 32;
        uint32_t baseH = sbase + (uint32_t)(2 * stg * SSTAGE) * 2u;
        uint32_t baseL = baseH + (uint32_t)SSTAGE * 2u;
#pragma unroll
        for (int it = 0; it < 2; it++) {
            int idx = tid + it * 256;           // 0..511: 16B groups
            int r = idx >> 2, g = idx & 3;      // row, 8-elem group
            int gr = bm0 + r;
            uint32_t sz = (gr < M) ? 16u : 0u;
            uint32_t doff = (uint32_t)(r * ASTRIDE + g * 8) * 2u;
            const uint16_t* sh = Ah + (size_t)gr * K + k0 + g * 8;
            const uint16_t* sl = Al + (size_t)gr * K + k0 + g * 8;
            cp16(baseH + doff, sh, sz);
            cp16(baseL + doff, sl, sz);
        }
        asm volatile("cp.async.commit_group;");
    };

    issue(0);
    for (int ch = 0; ch < nch; ch++) {
        if (ch + 1 < nch) issue(ch + 1);
        if (ch + 1 < nch) asm volatile("cp.async.wait_group 1;");
        else              asm volatile("cp.async.wait_group 0;");
        __syncthreads();
        int stg = ch & 1;
        uint16_t* AsH = sm + 2 * stg * SSTAGE;
        uint16_t* AsL = AsH + SSTAGE;
        int k0 = ch * 32;
#pragma unroll
        for (int ks = 0; ks < 2; ks++) {
            int kk = ks * 16;
            uint32_t ah[2][4], al[2][4];
#pragma unroll
            for (int i = 0; i < 2; i++) {
                int r = wm * 32 + i * 16 + lq;
                int base = r * ASTRIDE + kk + lr * 2;
                ah[i][0] = *(const uint32_t*)&AsH[base];
                ah[i][1] = *(const uint32_t*)&AsH[base + 8 * ASTRIDE];
                ah[i][2] = *(const uint32_t*)&AsH[base + 8];
                ah[i][3] = *(const uint32_t*)&AsH[base + 8 * ASTRIDE + 8];
                al[i][0] = *(const uint32_t*)&AsL[base];
                al[i][1] = *(const uint32_t*)&AsL[base + 8 * ASTRIDE];
                al[i][2] = *(const uint32_t*)&AsL[base + 8];
                al[i][3] = *(const uint32_t*)&AsL[base + 8 * ASTRIDE + 8];
            }
#pragma unroll
            for (int j = 0; j < 8; j++) {
                int n = wn * 64 + j * 8 + lq;
                int bb = n * KP + k0 + kk + lr * 2;
                uint32_t bh0 = *(const uint32_t*)&BsH[bb];
                uint32_t bh1 = *(const uint32_t*)&BsH[bb + 8];
                uint32_t bl0 = *(const uint32_t*)&BsL[bb];
                uint32_t bl1 = *(const uint32_t*)&BsL[bb + 8];
#pragma unroll
                for (int i = 0; i < 2; i++) {
                    mma16816(acc[i][j], ah[i], bh0, bh1);
                    mma16816(acc[i][j], al[i], bh0, bh1);
                    mma16816(acc[i][j], ah[i], bl0, bl1);
                }
            }
        }
        __syncthreads();
    }

    // epilogue: write fragments to g_tmp (+ packed att for cols 192-195)
#pragma unroll
    for (int i = 0; i < 2; i++) {
        int r0 = bm0 + wm * 32 + i * 16 + lq;
        int r1 = r0 + 8;
#pragma unroll
        for (int j = 0; j < 8; j++) {
            int col = n0 + wn * 64 + j * 8 + lr * 2;
            if (r0 < M) *(float2*)&g_tmp[r0 * ST + col] = make_float2(acc[i][j][0], acc[i][j][1]);
            if (r1 < M) *(float2*)&g_tmp[r1 * ST + col] = make_float2(acc[i][j][2], acc[i][j][3]);
        }
        // cols 192-195 live in (n0=128, wn=1, j=0, lr<2): lr=0 -> att.xy, lr=1 -> att.zw
        if (n0 == 128 && wn == 1 && lr < 2) {
            if (r0 < M) ((float2*)&g_att[r0])[lr] = make_float2(acc[i][0][0], acc[i][0][1]);
            if (r1 < M) ((float2*)&g_att[r1])[lr] = make_float2(acc[i][0][2], acc[i][0][3]);
        }
    }
}

// ---------------- per-destination aggregation ----------------
// one warp per destination node; per-edge {w0,w1,src} packed in g_ew4 ->
// one uniform LDG.128 + one gather LDG.128 per edge. 4-edge unroll.

__global__ __launch_bounds__(256) void gat_edge_kernel(const float* __restrict__ bAtt,
                                                       const float* __restrict__ bLin,
                                                       float* __restrict__ out,
                                                       int write_split) {
    int w = (blockIdx.x * blockDim.x + threadIdx.x) >> 5;
    int lane = threadIdx.x & 31;
    if (w >= NN) return;
    int beg = g_off[w], end = g_off[w + 1];
    int deg = end - beg;

    float den0 = 0.f, den1 = 0.f;
    float4 acc = make_float4(0.f, 0.f, 0.f, 0.f);
    int h = lane >> 4;        // head owned by this lane's feature slice
    int col = lane * 4;       // feature elements [col, col+4) of the 128-wide hs row
    int j = beg;
    for (; j + 4 <= end; j += 4) {
        float4 e0 = __ldg(&g_ew4[j]);
        float4 e1 = __ldg(&g_ew4[j + 1]);
        float4 e2 = __ldg(&g_ew4[j + 2]);
        float4 e3 = __ldg(&g_ew4[j + 3]);
        const float4 v0 = *(const float4*)&g_tmp[__float_as_int(e0.z) * ST + col];
        const float4 v1 = *(const float4*)&g_tmp[__float_as_int(e1.z) * ST + col];
        const float4 v2 = *(const float4*)&g_tmp[__float_as_int(e2.z) * ST + col];
        const float4 v3 = *(const float4*)&g_tmp[__float_as_int(e3.z) * ST + col];
        den0 += (e0.x + e1.x) + (e2.x + e3.x);
        den1 += (e0.y + e1.y) + (e2.y + e3.y);
        float w0 = h ? e0.y : e0.x;
        float w1 = h ? e1.y : e1.x;
        float w2 = h ? e2.y : e2.x;
        float w3 = h ? e3.y : e3.x;
        acc.x = fmaf(w0, v0.x, acc.x); acc.y = fmaf(w0, v0.y, acc.y);
        acc.z = fmaf(w0, v0.z, acc.z); acc.w = fmaf(w0, v0.w, acc.w);
        acc.x = fmaf(w1, v1.x, acc.x); acc.y = fmaf(w1, v1.y, acc.y);
        acc.z = fmaf(w1, v1.z, acc.z); acc.w = fmaf(w1, v1.w, acc.w);
        acc.x = fmaf(w2, v2.x, acc.x); acc.y = fmaf(w2, v2.y, acc.y);
        acc.z = fmaf(w2, v2.z, acc.z); acc.w = fmaf(w2, v2.w, acc.w);
        acc.x = fmaf(w3, v3.x, acc.x); acc.y = fmaf(w3, v3.y, acc.y);
        acc.z = fmaf(w3, v3.z, acc.z); acc.w = fmaf(w3, v3.w, acc.w);
    }
    for (; j < end; j++) {
        float4 e0 = __ldg(&g_ew4[j]);
        const float4 v0 = *(const float4*)&g_tmp[__float_as_int(e0.z) * ST + col];
        den0 += e0.x;
        den1 += e0.y;
        float w0 = h ? e0.y : e0.x;
        acc.x = fmaf(w0, v0.x, acc.x); acc.y = fmaf(w0, v0.y, acc.y);
        acc.z = fmaf(w0, v0.z, acc.z); acc.w = fmaf(w0, v0.w, acc.w);
    }
    float inv0 = deg > 0 ? 1.f / den0 : 0.f;
    float inv1 = deg > 0 ? 1.f / den1 : 0.f;
    float invh = h ? inv1 : inv0;
    float sx = acc.x * invh, sy = acc.y * invh, sz = acc.z * invh, sw = acc.w * invh;
    // combine heads: lanes 0..15 hold head0 elems [col,col+4), partner lane+16 holds head1
    float px = __shfl_xor_sync(0xffffffffu, sx, 16);
    float py = __shfl_xor_sync(0xffffffffu, sy, 16);
    float pz = __shfl_xor_sync(0xffffffffu, sz, 16);
    float pw = __shfl_xor_sync(0xffffffffu, sw, 16);
    if (lane < 16) {
        float4 skip = *(const float4*)&g_tmp[w * ST + 128 + col];
        float4 r;
        r.x = fmaxf(0.f, 0.5f * (sx + px) + bAtt[col + 0] + bLin[col + 0] + skip.x);
        r.y = fmaxf(0.f, 0.5f * (sy + py) + bAtt[col + 1] + bLin[col + 1] + skip.y);
        r.z = fmaxf(0.f, 0.5f * (sz + pz) + bAtt[col + 2] + bLin[col + 2] + skip.z);
        r.w = fmaxf(0.f, 0.5f * (sw + pw) + bAtt[col + 3] + bLin[col + 3] + skip.w);
        *(float4*)&out[w * 64 + col] = r;
        if (write_split) {
            uint16_t hh[4], ll[4];
            bf16_split(r.x, hh[0], ll[0]);
            bf16_split(r.y, hh[1], ll[1]);
            bf16_split(r.z, hh[2], ll[2]);
            bf16_split(r.w, hh[3], ll[3]);
            uint2 hp, lp;
            hp.x = (uint32_t)hh[0] | ((uint32_t)hh[1] << 16);
            hp.y = (uint32_t)hh[2] | ((uint32_t)hh[3] << 16);
            lp.x = (uint32_t)ll[0] | ((uint32_t)ll[1] << 16);
            lp.y = (uint32_t)ll[2] | ((uint32_t)ll[3] << 16);
            *(uint2*)&g_xh[w * 64 + col] = hp;
            *(uint2*)&g_xl[w * 64 + col] = lp;
        }
    }
}

// ---------------- launch ----------------

extern "C" void kernel_launch(void* const* d_in, const int* in_sizes, int n_in,
                              void* d_out, int out_size) {
    const float* x = (const float*)d_in[0];
    const int* ei = (const int*)d_in[1];
    const int* src = ei;
    const int* dst = ei + EE;
    const float* Ws[3] = {(const float*)d_in[2], (const float*)d_in[9], (const float*)d_in[16]};
    const float* Wd[3] = {(const float*)d_in[3], (const float*)d_in[10], (const float*)d_in[17]};
    const float* as_[3] = {(const float*)d_in[4], (const float*)d_in[11], (const float*)d_in[18]};
    const float* ad_[3] = {(const float*)d_in[5], (const float*)d_in[12], (const float*)d_in[19]};
    const float* b_[3] = {(const float*)d_in[6], (const float*)d_in[13], (const float*)d_in[20]};
    const float* Wl[3] = {(const float*)d_in[7], (const float*)d_in[14], (const float*)d_in[21]};
    const float* bl[3] = {(const float*)d_in[8], (const float*)d_in[15], (const float*)d_in[22]};
    float* out = (float*)d_out;

    float *h1, *h2;
    cudaGetSymbolAddress((void**)&h1, g_h1);
    cudaGetSymbolAddress((void**)&h2, g_h2);
    uint16_t *xh, *xl, *wh, *wl;
    cudaGetSymbolAddress((void**)&xh, g_xh);
    cudaGetSymbolAddress((void**)&xl, g_xl);
    cudaGetSymbolAddress((void**)&wh, g_wThb);
    cudaGetSymbolAddress((void**)&wl, g_wTlb);

    // side streams + events (created once; capture-safe fork-join)
    static cudaStream_t s1 = [] {
        cudaStream_t s;
        cudaStreamCreateWithFlags(&s, cudaStreamNonBlocking);
        return s;
    }();
    static cudaStream_t s2 = [] {
        cudaStream_t s;
        cudaStreamCreateWithFlags(&s, cudaStreamNonBlocking);
        return s;
    }();
    static cudaStream_t s3 = [] {
        cudaStream_t s;
        cudaStreamCreateWithFlags(&s, cudaStreamNonBlocking);
        return s;
    }();
    static cudaEvent_t evFork = [] {
        cudaEvent_t e;
        cudaEventCreateWithFlags(&e, cudaEventDisableTiming);
        return e;
    }();
    static cudaEvent_t evJoin = [] {
        cudaEvent_t e;
        cudaEventCreateWithFlags(&e, cudaEventDisableTiming);
        return e;
    }();
    static cudaEvent_t evW = [] {
        cudaEvent_t e;
        cudaEventCreateWithFlags(&e, cudaEventDisableTiming);
        return e;
    }();
    static cudaEvent_t evAtt = [] {
        cudaEvent_t e;
        cudaEventCreateWithFlags(&e, cudaEventDisableTiming);
        return e;
    }();
    static cudaEvent_t evEw = [] {
        cudaEvent_t e;
        cudaEventCreateWithFlags(&e, cudaEventDisableTiming);
        return e;
    }();

    // max dynamic smem (layer 1: KP = 136)
    int smem_max = (4 * SSTAGE + 2 * 128 * 136) * (int)sizeof(uint16_t);
    cudaFuncSetAttribute(sgemm_mma_kernel, cudaFuncAttributeMaxDynamicSharedMemorySize, smem_max);

    // fork
    cudaEventRecord(evFork, 0);
    cudaStreamWaitEvent(s1, evFork, 0);
    cudaStreamWaitEvent(s2, evFork, 0);

    // s1: CSR build (only needed by ew of layer 0)
    zero_cnt_kernel<<<(NN + 255) / 256, 256, 0, s1>>>();
    count_kernel<<<(EE + 255) / 256, 256, 0, s1>>>(dst);
    scan_kernel<<<1, 1024, 0, s1>>>();
    fill_kernel<<<(EE + 255) / 256, 256, 0, s1>>>(dst);
    cudaEventRecord(evJoin, s1);

    // s2: all three weight-concat kernels (depend only on input weights)
    {
        int din = 128;
        for (int l = 0; l < 3; l++) {
            wcat_kernel<<<(din * 256 + 255) / 256, 256, 0, s2>>>(
                Ws[l], Wd[l], Wl[l], as_[l], ad_[l], din,
                wh + (size_t)l * 256 * 128, wl + (size_t)l * 256 * 128);
            din = 64;
        }
        cudaEventRecord(evW, s2);
    }

    // main stream
    split_x_kernel<<<(NN * 32 + 255) / 256, 256>>>(x);
    cudaStreamWaitEvent(0, evW, 0);

    int din = 128;
    for (int l = 0; l < 3; l++) {
        float* out_ptr = (l == 0) ? h1 : (l == 1 ? h2 : out);
        int KP = din + 8;
        int smem = (4 * SSTAGE + 2 * 128 * KP) * (int)sizeof(uint16_t);
        const uint16_t* Bh = wh + (size_t)l * 256 * 128;
        const uint16_t* Bl = wl + (size_t)l * 256 * 128;
        dim3 gh(1, (NN + 127) / 128);

        // att+skip half first (produces g_att)
        sgemm_mma_kernel<<<gh, 256, smem>>>(xh, xl, Bh, Bl, NN, din, KP, 128);
        cudaEventRecord(evAtt, 0);

        // ew on side stream, overlapped with the hs half
        cudaStreamWaitEvent(s3, evAtt, 0);
        if (l == 0) cudaStreamWaitEvent(s3, evJoin, 0);   // ew needs g_pos
        ew_kernel<<<(EE + 255) / 256, 256, 0, s3>>>(src, dst);
        cudaEventRecord(evEw, s3);

        // hs half on main stream
        sgemm_mma_kernel<<<gh, 256, smem>>>(xh, xl, Bh, Bl, NN, din, KP, 0);

        cudaStreamWaitEvent(0, evEw, 0);
        gat_edge_kernel<<<(NN * 32 + 255) / 256, 256>>>(b_[l], bl[l], out_ptr, l < 2 ? 1 : 0);
        din = 64;
    }
}